// round 4
// baseline (speedup 1.0000x reference)
#include <cuda_runtime.h>
#include <cstdint>

#define BATCH 2
#define EMB   1024
#define SEQ   2048
#define NH    16
#define DH    64
#define KDIM  1024

// ---------------- scratch (__device__ globals; no allocs allowed) -----------
__device__ float g_qp[(size_t)BATCH * EMB * SEQ];   // Q proj [E][S]
__device__ float g_kp[(size_t)BATCH * EMB * SEQ];   // K proj [E][S]
__device__ float g_vp[(size_t)BATCH * EMB * SEQ];   // V proj [E][S]
__device__ float g_at[(size_t)BATCH * EMB * SEQ];   // attn out [E][S]

// ---------------- mma.sync helpers ------------------------------------------
__device__ __forceinline__ uint32_t smem_u32(const void* p) {
    uint32_t a;
    asm("{ .reg .u64 t; cvta.to.shared.u64 t, %1; cvt.u32.u64 %0, t; }"
        : "=r"(a) : "l"(p));
    return a;
}

__device__ __forceinline__ void mma16816(float* c, const uint32_t* a, const uint32_t* b) {
    asm volatile(
        "mma.sync.aligned.m16n8k16.row.col.f32.bf16.bf16.f32 "
        "{%0,%1,%2,%3}, {%4,%5,%6,%7}, {%8,%9}, {%0,%1,%2,%3};"
        : "+f"(c[0]), "+f"(c[1]), "+f"(c[2]), "+f"(c[3])
        : "r"(a[0]), "r"(a[1]), "r"(a[2]), "r"(a[3]), "r"(b[0]), "r"(b[1]));
}

#define LDSM_X4(r0, r1, r2, r3, addr)                                          \
    asm volatile("ldmatrix.sync.aligned.m8n8.x4.shared.b16 {%0,%1,%2,%3}, [%4];" \
                 : "=r"(r0), "=r"(r1), "=r"(r2), "=r"(r3) : "r"(addr))

#define LDSM_X4T(r0, r1, r2, r3, addr)                                         \
    asm volatile("ldmatrix.sync.aligned.m8n8.x4.trans.shared.b16 {%0,%1,%2,%3}, [%4];" \
                 : "=r"(r0), "=r"(r1), "=r"(r2), "=r"(r3) : "r"(addr))

#define STS_V2(addr, a, b)                                                     \
    asm volatile("st.shared.v2.b32 [%0], {%1, %2};" :: "r"(addr), "r"(a), "r"(b) : "memory")

// pack: low half = a, high half = b (memory element order: a then b)
#define CVT_BF16X2(res, a, b)                                                  \
    asm("cvt.rn.bf16x2.f32 %0, %1, %2;" : "=r"(res) : "f"(b), "f"(a))

// split a float4 into bf16-hi pair regs and bf16-lo pair regs
__device__ __forceinline__ void split4(const float4 v, uint32_t& h0, uint32_t& h1,
                                       uint32_t& l0, uint32_t& l1) {
    CVT_BF16X2(h0, v.x, v.y);
    CVT_BF16X2(h1, v.z, v.w);
    const float r0 = v.x - __uint_as_float(h0 << 16);
    const float r1 = v.y - __uint_as_float(h0 & 0xffff0000u);
    const float r2 = v.z - __uint_as_float(h1 << 16);
    const float r3 = v.w - __uint_as_float(h1 & 0xffff0000u);
    CVT_BF16X2(l0, r0, r1);
    CVT_BF16X2(l1, r2, r3);
}

// ---------------- GEMM via mma.sync ------------------------------------------
// C[b][m][n] = alpha * (sum_k W[m][k] * X[b][k][n] + bias[m])
// A = W row-major (k contiguous)  -> plain ldmatrix
// B = X k-major tile [32k][128n]  -> ldmatrix.x4.trans
// CTA 128m x 128n, BK=32, 8 warps (wm 0..3 -> m 32-chunks, wn 0..1 -> n 64-chunks)
#define LA 40      // A smem pitch in bf16 elems
#define LB 136     // B smem pitch in bf16 elems
#define AH_OFF 0
#define AL_OFF 10240
#define BH_OFF 20480
#define BL_OFF 29184
#define BUF_BYTES 37888
#define BIAS_OFF  75776
#define GB_SMEM   76288

__global__ void __launch_bounds__(256) gemm_mma(
    const float* __restrict__ X, const float* __restrict__ W,
    const float* __restrict__ bias, float* __restrict__ C, float alpha)
{
    extern __shared__ char smg[];
    const uint32_t sb = smem_u32(smg);
    const int tid = threadIdx.x, wid = tid >> 5, lane = tid & 31;
    const int n0 = blockIdx.x * 128, m0 = blockIdx.y * 128;
    const float* Xb = X + (size_t)blockIdx.z * KDIM * SEQ;
    float*       Cb = C + (size_t)blockIdx.z * EMB * SEQ;
    float* bias_s = (float*)(smg + BIAS_OFF);
    if (tid < 128) bias_s[tid] = bias[m0 + tid];

    const int wm = wid & 3;     // m 32-chunk
    const int wn = wid >> 2;    // n 64-chunk

    float acc[2][8][4];
#pragma unroll
    for (int ms = 0; ms < 2; ms++)
#pragma unroll
        for (int nt = 0; nt < 8; nt++)
#pragma unroll
            for (int i = 0; i < 4; i++) acc[ms][nt][i] = 0.f;

    // ldmatrix per-lane address components
    const int arow = lane & 15, ak8 = (lane >> 4) * 8;          // A: rows, k-half
    const int bj = lane >> 3, br = lane & 7;                    // B matrices
    const int bk = (bj & 1) * 8 + br, bn8 = (bj >> 1) * 8;      // B: k row, n-half

    float4 ra[4], rb[4];

    // ---- global tile load into regs ----
#define LOADG(kt) do {                                                         \
    _Pragma("unroll")                                                          \
    for (int i = 0; i < 4; i++) {                                              \
        const int e = i * 256 + tid;                                           \
        const int r = e >> 3, c = e & 7;                                       \
        ra[i] = *(const float4*)&W[(size_t)(m0 + r) * KDIM + (kt) * 32 + c * 4]; \
    }                                                                          \
    _Pragma("unroll")                                                          \
    for (int i = 0; i < 4; i++) {                                              \
        const int e = i * 256 + tid;                                           \
        const int r = e >> 5, c = e & 31;                                      \
        rb[i] = *(const float4*)&Xb[(size_t)((kt) * 32 + r) * SEQ + n0 + c * 4]; \
    }                                                                          \
} while (0)

    // ---- regs -> smem (convert to bf16 hi/lo) ----
#define STORES(buf) do {                                                       \
    const uint32_t base = sb + (buf) * BUF_BYTES;                              \
    _Pragma("unroll")                                                          \
    for (int i = 0; i < 4; i++) {                                              \
        const int e = i * 256 + tid;                                           \
        const int r = e >> 3, c = e & 7;                                       \
        uint32_t h0, h1, l0, l1;                                               \
        split4(ra[i], h0, h1, l0, l1);                                         \
        const uint32_t off = (uint32_t)(r * LA + c * 4) * 2;                   \
        STS_V2(base + AH_OFF + off, h0, h1);                                   \
        STS_V2(base + AL_OFF + off, l0, l1);                                   \
    }                                                                          \
    _Pragma("unroll")                                                          \
    for (int i = 0; i < 4; i++) {                                              \
        const int e = i * 256 + tid;                                           \
        const int r = e >> 5, c = e & 31;                                      \
        uint32_t h0, h1, l0, l1;                                               \
        split4(rb[i], h0, h1, l0, l1);                                         \
        const uint32_t off = (uint32_t)(r * LB + c * 4) * 2;                   \
        STS_V2(base + BH_OFF + off, h0, h1);                                   \
        STS_V2(base + BL_OFF + off, l0, l1);                                   \
    }                                                                          \
} while (0)

    LOADG(0);
    STORES(0);
    __syncthreads();

    const int NKT = KDIM / 32;
    for (int kt = 0; kt < NKT; kt++) {
        if (kt + 1 < NKT) LOADG(kt + 1);

        const uint32_t base = sb + (kt & 1) * BUF_BYTES;
#pragma unroll
        for (int ks = 0; ks < 2; ks++) {
            // A fragments (hi and lo) for the two 16-row subtiles
            uint32_t aF[2][4], aL[2][4];
#pragma unroll
            for (int ms = 0; ms < 2; ms++) {
                const uint32_t ao = (uint32_t)((wm * 32 + ms * 16 + arow) * LA
                                               + ks * 16 + ak8) * 2;
                LDSM_X4(aF[ms][0], aF[ms][1], aF[ms][2], aF[ms][3], base + AH_OFF + ao);
                LDSM_X4(aL[ms][0], aL[ms][1], aL[ms][2], aL[ms][3], base + AL_OFF + ao);
            }
#pragma unroll
            for (int nt16 = 0; nt16 < 4; nt16++) {
                uint32_t bH[4], bL[4];
                const uint32_t bo = (uint32_t)((ks * 16 + bk) * LB
                                               + wn * 64 + nt16 * 16 + bn8) * 2;
                LDSM_X4T(bH[0], bH[1], bH[2], bH[3], base + BH_OFF + bo);
                LDSM_X4T(bL[0], bL[1], bL[2], bL[3], base + BL_OFF + bo);
#pragma unroll
                for (int ms = 0; ms < 2; ms++) {
#pragma unroll
                    for (int s = 0; s < 2; s++) {
                        float* a4 = acc[ms][nt16 * 2 + s];
                        mma16816(a4, aF[ms], &bH[s * 2]);   // hi*hi
                        mma16816(a4, aF[ms], &bL[s * 2]);   // hi*lo
                        mma16816(a4, aL[ms], &bH[s * 2]);   // lo*hi
                    }
                }
            }
        }
        __syncthreads();
        if (kt + 1 < NKT) {
            STORES((kt + 1) & 1);
            __syncthreads();
        }
    }

    // ---- epilogue: accs -> smem [128m][128n] -> coalesced global ----
    __syncthreads();
    float* Cs = (float*)smg;                 // 128 x 132 floats
    {
        const int rr = lane >> 2, cc = (lane & 3) * 2;
#pragma unroll
        for (int ms = 0; ms < 2; ms++)
#pragma unroll
            for (int nt = 0; nt < 8; nt++) {
                const int r = wm * 32 + ms * 16 + rr;
                const int c = wn * 64 + nt * 8 + cc;
                Cs[r * 132 + c]           = acc[ms][nt][0];
                Cs[r * 132 + c + 1]       = acc[ms][nt][1];
                Cs[(r + 8) * 132 + c]     = acc[ms][nt][2];
                Cs[(r + 8) * 132 + c + 1] = acc[ms][nt][3];
            }
    }
    __syncthreads();
#pragma unroll
    for (int i = 0; i < 16; i++) {
        const int e = i * 256 + tid;
        const int r = e >> 5, c = e & 31;
        float4 v = *(const float4*)&Cs[r * 132 + c * 4];
        const float bi = bias_s[r];
        v.x = alpha * (v.x + bi); v.y = alpha * (v.y + bi);
        v.z = alpha * (v.z + bi); v.w = alpha * (v.w + bi);
        *(float4*)&Cb[(size_t)(m0 + r) * SEQ + n0 + c * 4] = v;
    }
}

// ---------------- fused SIMT attention (validated in R1) ---------------------
#define LQ 68
#define LV 65
static const int ATTN_SMEM_BYTES = (3 * 64 * LQ + 64 * LV) * (int)sizeof(float);

__global__ void __launch_bounds__(256) attn_kernel(
    const float* __restrict__ QP, const float* __restrict__ KP,
    const float* __restrict__ VP, const float* __restrict__ MASK,
    float* __restrict__ OUTP)
{
    extern __shared__ float sma[];
    float* Qs = sma;
    float* Ks = Qs + 64 * LQ;
    float* Ps = Ks + 64 * LQ;
    float* Vs = Ps + 64 * LQ;

    const int tid = threadIdx.x;
    const int b = blockIdx.z, h = blockIdx.y;
    const int q0 = blockIdx.x * 64;

    const float* Qg = QP + ((size_t)b * EMB + h * DH) * SEQ + q0;
    const float* Kg = KP + ((size_t)b * EMB + h * DH) * SEQ;
    const float* Vg = VP + ((size_t)b * EMB + h * DH) * SEQ;
    const float* Mg = MASK + (size_t)b * SEQ * SEQ + q0;
    float*       Og = OUTP + ((size_t)b * EMB + h * DH) * SEQ + q0;

    const int tk = tid & 15;
    const int tq = tid >> 4;

#pragma unroll
    for (int it = 0; it < 4; it++) {
        const int e = tid + it * 256;
        const int c = e >> 4, x4 = (e & 15) * 4;
        *(float4*)&Qs[c * LQ + x4] = *(const float4*)&Qg[(size_t)c * SEQ + x4];
    }

    float m_r[4], l_r[4], o_r[4][4];
#pragma unroll
    for (int j = 0; j < 4; j++) { m_r[j] = -1e30f; l_r[j] = 0.f; }
#pragma unroll
    for (int i = 0; i < 4; i++)
#pragma unroll
        for (int j = 0; j < 4; j++) o_r[i][j] = 0.f;

    for (int kt = 0; kt < SEQ / 64; kt++) {
        const int k0 = kt * 64;
        __syncthreads();
#pragma unroll
        for (int it = 0; it < 4; it++) {
            const int e = tid + it * 256;
            const int c = e >> 4, x4 = (e & 15) * 4;
            *(float4*)&Ks[c * LQ + x4] =
                *(const float4*)&Kg[(size_t)c * SEQ + k0 + x4];
            float4 vv = *(const float4*)&Vg[(size_t)c * SEQ + k0 + x4];
            Vs[c * LV + x4 + 0] = vv.x; Vs[c * LV + x4 + 1] = vv.y;
            Vs[c * LV + x4 + 2] = vv.z; Vs[c * LV + x4 + 3] = vv.w;
        }
        __syncthreads();

        float acc[4][4];
#pragma unroll
        for (int i = 0; i < 4; i++) {
            float4 mr = *(const float4*)&Mg[(size_t)(k0 + tk * 4 + i) * SEQ + tq * 4];
            acc[i][0] = mr.x; acc[i][1] = mr.y; acc[i][2] = mr.z; acc[i][3] = mr.w;
        }
#pragma unroll 8
        for (int c = 0; c < 64; c++) {
            float kk[4], qq[4];
            *(float4*)kk = *(const float4*)&Ks[c * LQ + tk * 4];
            *(float4*)qq = *(const float4*)&Qs[c * LQ + tq * 4];
#pragma unroll
            for (int i = 0; i < 4; i++)
#pragma unroll
                for (int j = 0; j < 4; j++)
                    acc[i][j] += kk[i] * qq[j];
        }

        float p[4][4], fs[4];
#pragma unroll
        for (int j = 0; j < 4; j++) {
            float mx = fmaxf(fmaxf(acc[0][j], acc[1][j]), fmaxf(acc[2][j], acc[3][j]));
#pragma unroll
            for (int off = 1; off < 16; off <<= 1)
                mx = fmaxf(mx, __shfl_xor_sync(0xffffffffu, mx, off));
            const float mnew = fmaxf(m_r[j], mx);
            fs[j] = __expf(m_r[j] - mnew);
            float ts = 0.f;
#pragma unroll
            for (int i = 0; i < 4; i++) {
                p[i][j] = __expf(acc[i][j] - mnew);
                ts += p[i][j];
            }
#pragma unroll
            for (int off = 1; off < 16; off <<= 1)
                ts += __shfl_xor_sync(0xffffffffu, ts, off);
            l_r[j] = l_r[j] * fs[j] + ts;
            m_r[j] = mnew;
        }

#pragma unroll
        for (int i = 0; i < 4; i++)
            *(float4*)&Ps[(tk * 4 + i) * LQ + tq * 4] =
                make_float4(p[i][0], p[i][1], p[i][2], p[i][3]);

#pragma unroll
        for (int i = 0; i < 4; i++)
#pragma unroll
            for (int j = 0; j < 4; j++) o_r[i][j] *= fs[j];
        __syncwarp();

#pragma unroll 8
        for (int k = 0; k < 64; k++) {
            float pp[4];
            *(float4*)pp = *(const float4*)&Ps[k * LQ + tq * 4];
            const float v0 = Vs[(tk +  0) * LV + k];
            const float v1 = Vs[(tk + 16) * LV + k];
            const float v2 = Vs[(tk + 32) * LV + k];
            const float v3 = Vs[(tk + 48) * LV + k];
#pragma unroll
            for (int j = 0; j < 4; j++) {
                o_r[0][j] += v0 * pp[j];
                o_r[1][j] += v1 * pp[j];
                o_r[2][j] += v2 * pp[j];
                o_r[3][j] += v3 * pp[j];
            }
        }
        __syncwarp();
    }

    float il[4];
#pragma unroll
    for (int j = 0; j < 4; j++) il[j] = 1.f / l_r[j];
#pragma unroll
    for (int i = 0; i < 4; i++) {
        float4 r;
        r.x = o_r[i][0] * il[0]; r.y = o_r[i][1] * il[1];
        r.z = o_r[i][2] * il[2]; r.w = o_r[i][3] * il[3];
        *(float4*)&Og[(size_t)(tk + 16 * i) * SEQ + tq * 4] = r;
    }
}

// ---------------------------------------------------------------------------
extern "C" void kernel_launch(void* const* d_in, const int* in_sizes, int n_in,
                              void* d_out, int out_size)
{
    const float* q   = (const float*)d_in[0];
    const float* k   = (const float*)d_in[1];
    const float* v   = (const float*)d_in[2];
    const float* msk = (const float*)d_in[3];
    const float* Wq  = (const float*)d_in[4];
    const float* bq  = (const float*)d_in[5];
    const float* Wk  = (const float*)d_in[6];
    const float* bk  = (const float*)d_in[7];
    const float* Wv  = (const float*)d_in[8];
    const float* bv  = (const float*)d_in[9];
    const float* Wo  = (const float*)d_in[10];
    const float* bo  = (const float*)d_in[11];
    float* out = (float*)d_out;

    void *pqp, *pkp, *pvp, *pat;
    cudaGetSymbolAddress(&pqp, g_qp);
    cudaGetSymbolAddress(&pkp, g_kp);
    cudaGetSymbolAddress(&pvp, g_vp);
    cudaGetSymbolAddress(&pat, g_at);

    cudaFuncSetAttribute(gemm_mma, cudaFuncAttributeMaxDynamicSharedMemorySize, GB_SMEM);
    cudaFuncSetAttribute(attn_kernel, cudaFuncAttributeMaxDynamicSharedMemorySize,
                         ATTN_SMEM_BYTES);

    dim3 gg(SEQ / 128, EMB / 128, BATCH);
    gemm_mma<<<gg, 256, GB_SMEM>>>(q, Wq, bq, (float*)pqp, 0.125f);
    gemm_mma<<<gg, 256, GB_SMEM>>>(k, Wk, bk, (float*)pkp, 1.0f);
    gemm_mma<<<gg, 256, GB_SMEM>>>(v, Wv, bv, (float*)pvp, 1.0f);

    dim3 ga(SEQ / 64, NH, BATCH);
    attn_kernel<<<ga, 256, ATTN_SMEM_BYTES>>>(
        (const float*)pqp, (const float*)pkp, (const float*)pvp, msk, (float*)pat);

    gemm_mma<<<gg, 256, GB_SMEM>>>((const float*)pat, Wo, bo, out, 1.0f);
}

// round 6
// speedup vs baseline: 1.5997x; 1.5997x over previous
#include <cuda_runtime.h>
#include <cstdint>

#define BATCH 2
#define EMB   1024
#define SEQ   2048
#define NH    16
#define DH    64
#define KDIM  1024
#define LOG2E 1.4426950408889634f
typedef unsigned short ushort_t;

__device__ float g_qp[(size_t)BATCH * EMB * SEQ];
__device__ float g_kp[(size_t)BATCH * EMB * SEQ];
__device__ float g_vp[(size_t)BATCH * EMB * SEQ];
__device__ float g_at[(size_t)BATCH * EMB * SEQ];

__device__ __forceinline__ uint32_t smem_u32(const void* p) {
    uint32_t a;
    asm("{ .reg .u64 t; cvta.to.shared.u64 t, %1; cvt.u32.u64 %0, t; }" : "=r"(a) : "l"(p));
    return a;
}
__device__ __forceinline__ void mma16816(float* c, const uint32_t* a, const uint32_t* b) {
    asm volatile("mma.sync.aligned.m16n8k16.row.col.f32.bf16.bf16.f32 "
        "{%0,%1,%2,%3}, {%4,%5,%6,%7}, {%8,%9}, {%0,%1,%2,%3};"
        : "+f"(c[0]), "+f"(c[1]), "+f"(c[2]), "+f"(c[3])
        : "r"(a[0]), "r"(a[1]), "r"(a[2]), "r"(a[3]), "r"(b[0]), "r"(b[1]));
}
#define LDSM_X4(r0,r1,r2,r3,addr) \
    asm volatile("ldmatrix.sync.aligned.m8n8.x4.shared.b16 {%0,%1,%2,%3}, [%4];" \
                 : "=r"(r0),"=r"(r1),"=r"(r2),"=r"(r3) : "r"(addr))
#define LDSM_X4T(r0,r1,r2,r3,addr) \
    asm volatile("ldmatrix.sync.aligned.m8n8.x4.trans.shared.b16 {%0,%1,%2,%3}, [%4];" \
                 : "=r"(r0),"=r"(r1),"=r"(r2),"=r"(r3) : "r"(addr))
#define STS_V2(addr,a,b) \
    asm volatile("st.shared.v2.b32 [%0], {%1, %2};" :: "r"(addr), "r"(a), "r"(b) : "memory")
#define CVT_BF16X2(res,a,b) asm("cvt.rn.bf16x2.f32 %0, %1, %2;" : "=r"(res) : "f"(b), "f"(a))
#define EX2F(y,x) asm("ex2.approx.f32 %0, %1;" : "=f"(y) : "f"(x))

__device__ __forceinline__ void split4(const float4 v, uint32_t& h0, uint32_t& h1,
                                       uint32_t& l0, uint32_t& l1) {
    CVT_BF16X2(h0, v.x, v.y);
    CVT_BF16X2(h1, v.z, v.w);
    const float r0 = v.x - __uint_as_float(h0 << 16);
    const float r1 = v.y - __uint_as_float(h0 & 0xffff0000u);
    const float r2 = v.z - __uint_as_float(h1 << 16);
    const float r3 = v.w - __uint_as_float(h1 & 0xffff0000u);
    CVT_BF16X2(l0, r0, r1);
    CVT_BF16X2(l1, r2, r3);
}

// ---------------- GEMM via mma.sync (R3-validated, unchanged) ----------------
#define LA 40
#define LB 136
#define AH_OFF 0
#define AL_OFF 10240
#define BH_OFF 20480
#define BL_OFF 29184
#define BUF_BYTES 37888
#define BIAS_OFF  75776
#define GB_SMEM   76288

__global__ void __launch_bounds__(256) gemm_mma(
    const float* __restrict__ X, const float* __restrict__ W,
    const float* __restrict__ bias, float* __restrict__ C, float alpha)
{
    extern __shared__ char smg[];
    const uint32_t sb = smem_u32(smg);
    const int tid = threadIdx.x, wid = tid >> 5, lane = tid & 31;
    const int n0 = blockIdx.x * 128, m0 = blockIdx.y * 128;
    const float* Xb = X + (size_t)blockIdx.z * KDIM * SEQ;
    float*       Cb = C + (size_t)blockIdx.z * EMB * SEQ;
    float* bias_s = (float*)(smg + BIAS_OFF);
    if (tid < 128) bias_s[tid] = bias[m0 + tid];

    const int wm = wid & 3, wn = wid >> 2;
    float acc[2][8][4];
#pragma unroll
    for (int ms = 0; ms < 2; ms++)
#pragma unroll
        for (int nt = 0; nt < 8; nt++)
#pragma unroll
            for (int i = 0; i < 4; i++) acc[ms][nt][i] = 0.f;

    const int arow = lane & 15, ak8 = (lane >> 4) * 8;
    const int bj = lane >> 3, br = lane & 7;
    const int bk = (bj & 1) * 8 + br, bn8 = (bj >> 1) * 8;
    float4 ra[4], rb[4];

#define LOADG(kt) do {                                                         \
    _Pragma("unroll")                                                          \
    for (int i = 0; i < 4; i++) {                                              \
        const int e = i * 256 + tid;                                           \
        const int r = e >> 3, c = e & 7;                                       \
        ra[i] = *(const float4*)&W[(size_t)(m0 + r) * KDIM + (kt) * 32 + c * 4]; \
    }                                                                          \
    _Pragma("unroll")                                                          \
    for (int i = 0; i < 4; i++) {                                              \
        const int e = i * 256 + tid;                                           \
        const int r = e >> 5, c = e & 31;                                      \
        rb[i] = *(const float4*)&Xb[(size_t)((kt) * 32 + r) * SEQ + n0 + c * 4]; \
    }                                                                          \
} while (0)

#define STORES(buf) do {                                                       \
    const uint32_t base = sb + (buf) * BUF_BYTES;                              \
    _Pragma("unroll")                                                          \
    for (int i = 0; i < 4; i++) {                                              \
        const int e = i * 256 + tid;                                           \
        const int r = e >> 3, c = e & 7;                                       \
        uint32_t h0, h1, l0, l1;                                               \
        split4(ra[i], h0, h1, l0, l1);                                         \
        const uint32_t off = (uint32_t)(r * LA + c * 4) * 2;                   \
        STS_V2(base + AH_OFF + off, h0, h1);                                   \
        STS_V2(base + AL_OFF + off, l0, l1);                                   \
    }                                                                          \
    _Pragma("unroll")                                                          \
    for (int i = 0; i < 4; i++) {                                              \
        const int e = i * 256 + tid;                                           \
        const int r = e >> 5, c = e & 31;                                      \
        uint32_t h0, h1, l0, l1;                                               \
        split4(rb[i], h0, h1, l0, l1);                                         \
        const uint32_t off = (uint32_t)(r * LB + c * 4) * 2;                   \
        STS_V2(base + BH_OFF + off, h0, h1);                                   \
        STS_V2(base + BL_OFF + off, l0, l1);                                   \
    }                                                                          \
} while (0)

    LOADG(0);
    STORES(0);
    __syncthreads();

    const int NKT = KDIM / 32;
    for (int kt = 0; kt < NKT; kt++) {
        if (kt + 1 < NKT) LOADG(kt + 1);
        const uint32_t base = sb + (kt & 1) * BUF_BYTES;
#pragma unroll
        for (int ks = 0; ks < 2; ks++) {
            uint32_t aF[2][4], aL[2][4];
#pragma unroll
            for (int ms = 0; ms < 2; ms++) {
                const uint32_t ao = (uint32_t)((wm * 32 + ms * 16 + arow) * LA + ks * 16 + ak8) * 2;
                LDSM_X4(aF[ms][0], aF[ms][1], aF[ms][2], aF[ms][3], base + AH_OFF + ao);
                LDSM_X4(aL[ms][0], aL[ms][1], aL[ms][2], aL[ms][3], base + AL_OFF + ao);
            }
#pragma unroll
            for (int nt16 = 0; nt16 < 4; nt16++) {
                uint32_t bH[4], bL[4];
                const uint32_t bo = (uint32_t)((ks * 16 + bk) * LB + wn * 64 + nt16 * 16 + bn8) * 2;
                LDSM_X4T(bH[0], bH[1], bH[2], bH[3], base + BH_OFF + bo);
                LDSM_X4T(bL[0], bL[1], bL[2], bL[3], base + BL_OFF + bo);
#pragma unroll
                for (int ms = 0; ms < 2; ms++)
#pragma unroll
                    for (int s = 0; s < 2; s++) {
                        float* a4 = acc[ms][nt16 * 2 + s];
                        mma16816(a4, aF[ms], &bH[s * 2]);
                        mma16816(a4, aF[ms], &bL[s * 2]);
                        mma16816(a4, aL[ms], &bH[s * 2]);
                    }
            }
        }
        __syncthreads();
        if (kt + 1 < NKT) { STORES((kt + 1) & 1); __syncthreads(); }
    }

    __syncthreads();
    float* Cs = (float*)smg;
    {
        const int rr = lane >> 2, cc = (lane & 3) * 2;
#pragma unroll
        for (int ms = 0; ms < 2; ms++)
#pragma unroll
            for (int nt = 0; nt < 8; nt++) {
                const int r = wm * 32 + ms * 16 + rr;
                const int c = wn * 64 + nt * 8 + cc;
                Cs[r * 132 + c]           = acc[ms][nt][0];
                Cs[r * 132 + c + 1]       = acc[ms][nt][1];
                Cs[(r + 8) * 132 + c]     = acc[ms][nt][2];
                Cs[(r + 8) * 132 + c + 1] = acc[ms][nt][3];
            }
    }
    __syncthreads();
#pragma unroll
    for (int i = 0; i < 16; i++) {
        const int e = i * 256 + tid;
        const int r = e >> 5, c = e & 31;
        float4 v = *(const float4*)&Cs[r * 132 + c * 4];
        const float bi = bias_s[r];
        v.x = alpha * (v.x + bi); v.y = alpha * (v.y + bi);
        v.z = alpha * (v.z + bi); v.w = alpha * (v.w + bi);
        *(float4*)&Cb[(size_t)(m0 + r) * SEQ + n0 + c * 4] = v;
    }
}

// ---------------- tensorized flash attention --------------------------------
// CTA: (b, h, 128-q tile); warp w owns q rows [16w,16w+16).
// S = Q^T K (m=q, n=key, k=dh) with mask preloaded in accum; exp2 inline;
// O = P V^T (m=q, n=dh, k=key), P reused from regs. bf16 hi/lo 3-pass both.
#define PQ 136         // Q smem pitch (halves)
#define PK 72          // K/V smem pitch (halves)
#define AQH 0
#define AQL 17408
#define AKH 0
#define AKL 9216
#define AVH 18432
#define AVL 27648
#define AT_SMEM 36864

__global__ void __launch_bounds__(256) attn_mma(
    const float* __restrict__ QP, const float* __restrict__ KP,
    const float* __restrict__ VP, const float* __restrict__ MASK,
    float* __restrict__ OUTP)
{
    extern __shared__ char sma[];
    const uint32_t sb = smem_u32(sma);
    const int tid = threadIdx.x, wid = tid >> 5, lane = tid & 31;
    const int b = blockIdx.z, h = blockIdx.y, q0 = blockIdx.x * 128;

    const float* Qg = QP + ((size_t)b * EMB + h * DH) * SEQ + q0;
    const float* Kg = KP + ((size_t)b * EMB + h * DH) * SEQ;
    const float* Vg = VP + ((size_t)b * EMB + h * DH) * SEQ;
    const float* Mg = MASK + (size_t)b * SEQ * SEQ;
    float*       Og = OUTP + ((size_t)b * EMB + h * DH) * SEQ + q0;

    // ---- stage Q (64 dh x 128 q), fold LOG2E, convert hi/lo ----
#pragma unroll
    for (int i = 0; i < 8; i++) {
        const int e = i * 256 + tid;
        const int r = e >> 5, c = (e & 31) * 4;
        float4 v = *(const float4*)&Qg[(size_t)r * SEQ + c];
        v.x *= LOG2E; v.y *= LOG2E; v.z *= LOG2E; v.w *= LOG2E;
        uint32_t h0, h1, l0, l1;
        split4(v, h0, h1, l0, l1);
        const uint32_t off = (uint32_t)(r * PQ + c) * 2;
        STS_V2(sb + AQH + off, h0, h1);
        STS_V2(sb + AQL + off, l0, l1);
    }
    __syncthreads();

    // ---- Q fragments to registers (A via trans-ldmatrix from [k][m]) ----
    const int arow_k = (lane & 7) + ((lane >> 4) << 3);
    const int amcol  = ((lane >> 3) & 1) * 8;
    uint32_t qh[4][4], ql[4][4];
#pragma unroll
    for (int ks = 0; ks < 4; ks++) {
        const uint32_t ao = (uint32_t)((ks * 16 + arow_k) * PQ + wid * 16 + amcol) * 2;
        LDSM_X4T(qh[ks][0], qh[ks][1], qh[ks][2], qh[ks][3], sb + AQH + ao);
        LDSM_X4T(ql[ks][0], ql[ks][1], ql[ks][2], ql[ks][3], sb + AQL + ao);
    }
    __syncthreads();

    const int bj = lane >> 3, br = lane & 7;
    const int bk = (bj & 1) * 8 + br, bn8 = (bj >> 1) * 8;

    float o[8][4];
#pragma unroll
    for (int d = 0; d < 8; d++)
#pragma unroll
        for (int j = 0; j < 4; j++) o[d][j] = 0.f;
    float lsum0 = 0.f, lsum1 = 0.f;

    const int qr = wid * 16 + (lane >> 2);      // this thread's q row (c0/c1)
    const int krow2 = 2 * (lane & 3);           // key offset within n8

    ushort_t* vth = (ushort_t*)(sma + AVH);
    ushort_t* vtl = (ushort_t*)(sma + AVL);

    for (int kt = 0; kt < SEQ / 64; kt++) {
        const int k0 = kt * 64;
        __syncthreads();
        // ---- stage K [64 dh][64 key] hi/lo; V transposed [64 key][64 dh] ----
#pragma unroll
        for (int i = 0; i < 4; i++) {
            const int e = i * 256 + tid;
            const int r = e >> 4, c = (e & 15) * 4;
            float4 kv = *(const float4*)&Kg[(size_t)r * SEQ + k0 + c];
            uint32_t h0, h1, l0, l1;
            split4(kv, h0, h1, l0, l1);
            const uint32_t off = (uint32_t)(r * PK + c) * 2;
            STS_V2(sb + AKH + off, h0, h1);
            STS_V2(sb + AKL + off, l0, l1);
            float4 vv = *(const float4*)&Vg[(size_t)r * SEQ + k0 + c];
            split4(vv, h0, h1, l0, l1);
            vth[(c + 0) * PK + r] = (ushort_t)(h0 & 0xffff);
            vth[(c + 1) * PK + r] = (ushort_t)(h0 >> 16);
            vth[(c + 2) * PK + r] = (ushort_t)(h1 & 0xffff);
            vth[(c + 3) * PK + r] = (ushort_t)(h1 >> 16);
            vtl[(c + 0) * PK + r] = (ushort_t)(l0 & 0xffff);
            vtl[(c + 1) * PK + r] = (ushort_t)(l0 >> 16);
            vtl[(c + 2) * PK + r] = (ushort_t)(l1 & 0xffff);
            vtl[(c + 3) * PK + r] = (ushort_t)(l1 >> 16);
        }
        __syncthreads();

        // ---- S accum init = mask * LOG2E ----
        float s[8][4];
#pragma unroll
        for (int nt = 0; nt < 8; nt++) {
            const float* mp = Mg + (size_t)(k0 + nt * 8 + krow2) * SEQ + q0 + qr;
            s[nt][0] = mp[0]   * LOG2E;
            s[nt][1] = mp[SEQ] * LOG2E;
            s[nt][2] = mp[8]   * LOG2E;
            s[nt][3] = mp[SEQ + 8] * LOG2E;
        }
        // ---- QK mma (3-pass) ----
#pragma unroll
        for (int ks = 0; ks < 4; ks++)
#pragma unroll
            for (int np = 0; np < 4; np++) {
                uint32_t kh[4], kl[4];
                const uint32_t bo = (uint32_t)((ks * 16 + bk) * PK + np * 16 + bn8) * 2;
                LDSM_X4T(kh[0], kh[1], kh[2], kh[3], sb + AKH + bo);
                LDSM_X4T(kl[0], kl[1], kl[2], kl[3], sb + AKL + bo);
#pragma unroll
                for (int s2 = 0; s2 < 2; s2++) {
                    float* a4 = s[np * 2 + s2];
                    mma16816(a4, qh[ks], &kh[s2 * 2]);
                    mma16816(a4, qh[ks], &kl[s2 * 2]);
                    mma16816(a4, ql[ks], &kh[s2 * 2]);
                }
            }
        // ---- exp2, row sums, pack P into A-frags ----
        float rs0 = 0.f, rs1 = 0.f;
#pragma unroll
        for (int nt = 0; nt < 8; nt++) {
#pragma unroll
            for (int j = 0; j < 4; j++) EX2F(s[nt][j], s[nt][j]);
            rs0 += s[nt][0] + s[nt][1];
            rs1 += s[nt][2] + s[nt][3];
        }
        rs0 += __shfl_xor_sync(0xffffffffu, rs0, 1);
        rs0 += __shfl_xor_sync(0xffffffffu, rs0, 2);
        rs1 += __shfl_xor_sync(0xffffffffu, rs1, 1);
        rs1 += __shfl_xor_sync(0xffffffffu, rs1, 2);
        lsum0 += rs0;
        lsum1 += rs1;

        uint32_t pah[4][4], pal[4][4];
#pragma unroll
        for (int ks = 0; ks < 4; ks++) {
            const float* u = s[ks * 2];
            const float* w = s[ks * 2 + 1];
            CVT_BF16X2(pah[ks][0], u[0], u[1]);
            CVT_BF16X2(pah[ks][1], u[2], u[3]);
            CVT_BF16X2(pah[ks][2], w[0], w[1]);
            CVT_BF16X2(pah[ks][3], w[2], w[3]);
            float t0 = u[0] - __uint_as_float(pah[ks][0] << 16);
            float t1 = u[1] - __uint_as_float(pah[ks][0] & 0xffff0000u);
            float t2 = u[2] - __uint_as_float(pah[ks][1] << 16);
            float t3 = u[3] - __uint_as_float(pah[ks][1] & 0xffff0000u);
            CVT_BF16X2(pal[ks][0], t0, t1);
            CVT_BF16X2(pal[ks][1], t2, t3);
            t0 = w[0] - __uint_as_float(pah[ks][2] << 16);
            t1 = w[1] - __uint_as_float(pah[ks][2] & 0xffff0000u);
            t2 = w[2] - __uint_as_float(pah[ks][3] << 16);
            t3 = w[3] - __uint_as_float(pah[ks][3] & 0xffff0000u);
            CVT_BF16X2(pal[ks][2], t0, t1);
            CVT_BF16X2(pal[ks][3], t2, t3);
        }
        // ---- PV mma: O += P @ V^T (3-pass) ----
#pragma unroll
        for (int ks = 0; ks < 4; ks++)
#pragma unroll
            for (int dp = 0; dp < 4; dp++) {
                uint32_t vh[4], vl[4];
                const uint32_t bo = (uint32_t)((ks * 16 + bk) * PK + dp * 16 + bn8) * 2;
                LDSM_X4T(vh[0], vh[1], vh[2], vh[3], sb + AVH + bo);
                LDSM_X4T(vl[0], vl[1], vl[2], vl[3], sb + AVL + bo);
#pragma unroll
                for (int s2 = 0; s2 < 2; s2++) {
                    float* a4 = o[dp * 2 + s2];
                    mma16816(a4, pah[ks], &vh[s2 * 2]);
                    mma16816(a4, pah[ks], &vl[s2 * 2]);
                    mma16816(a4, pal[ks], &vh[s2 * 2]);
                }
            }
    }

    // ---- normalize, transpose via smem, coalesced [E][S] store ----
    const float inv0 = 1.f / lsum0, inv1 = 1.f / lsum1;
    __syncthreads();
    float* Os = (float*)sma;   // [64 dh][132]
#pragma unroll
    for (int d = 0; d < 8; d++) {
        const int dc = d * 8 + krow2;
        Os[dc * 132 + qr]           = o[d][0] * inv0;
        Os[(dc + 1) * 132 + qr]     = o[d][1] * inv0;
        Os[dc * 132 + qr + 8]       = o[d][2] * inv1;
        Os[(dc + 1) * 132 + qr + 8] = o[d][3] * inv1;
    }
    __syncthreads();
#pragma unroll
    for (int i = 0; i < 8; i++) {
        const int e = i * 256 + tid;
        const int r = e >> 5, c = (e & 31) * 4;
        *(float4*)&Og[(size_t)r * SEQ + c] = *(const float4*)&Os[r * 132 + c];
    }
}

// ---------------------------------------------------------------------------
extern "C" void kernel_launch(void* const* d_in, const int* in_sizes, int n_in,
                              void* d_out, int out_size)
{
    const float* q   = (const float*)d_in[0];
    const float* k   = (const float*)d_in[1];
    const float* v   = (const float*)d_in[2];
    const float* msk = (const float*)d_in[3];
    const float* Wq  = (const float*)d_in[4];
    const float* bq  = (const float*)d_in[5];
    const float* Wk  = (const float*)d_in[6];
    const float* bk  = (const float*)d_in[7];
    const float* Wv  = (const float*)d_in[8];
    const float* bv  = (const float*)d_in[9];
    const float* Wo  = (const float*)d_in[10];
    const float* bo  = (const float*)d_in[11];
    float* out = (float*)d_out;

    void *pqp, *pkp, *pvp, *pat;
    cudaGetSymbolAddress(&pqp, g_qp);
    cudaGetSymbolAddress(&pkp, g_kp);
    cudaGetSymbolAddress(&pvp, g_vp);
    cudaGetSymbolAddress(&pat, g_at);

    cudaFuncSetAttribute(gemm_mma, cudaFuncAttributeMaxDynamicSharedMemorySize, GB_SMEM);

    dim3 gg(SEQ / 128, EMB / 128, BATCH);
    gemm_mma<<<gg, 256, GB_SMEM>>>(q, Wq, bq, (float*)pqp, 0.125f);
    gemm_mma<<<gg, 256, GB_SMEM>>>(k, Wk, bk, (float*)pkp, 1.0f);
    gemm_mma<<<gg, 256, GB_SMEM>>>(v, Wv, bv, (float*)pvp, 1.0f);

    dim3 ga(SEQ / 128, NH, BATCH);
    attn_mma<<<ga, 256, AT_SMEM>>>(
        (const float*)pqp, (const float*)pkp, (const float*)pvp, msk, (float*)pat);

    gemm_mma<<<gg, 256, GB_SMEM>>>((const float*)pat, Wo, bo, out, 1.0f);
}

// round 7
// speedup vs baseline: 1.9414x; 1.2136x over previous
#include <cuda_runtime.h>
#include <cstdint>

#define BATCH 2
#define EMB   1024
#define SEQ   2048
#define NH    16
#define DH    64
#define KDIM  1024
#define LOG2E 1.4426950408889634f
typedef unsigned short ushort_t;

__device__ float g_qp[(size_t)BATCH * EMB * SEQ];
__device__ float g_kp[(size_t)BATCH * EMB * SEQ];
__device__ float g_vp[(size_t)BATCH * EMB * SEQ];
__device__ float g_at[(size_t)BATCH * EMB * SEQ];

__device__ __forceinline__ uint32_t smem_u32(const void* p) {
    uint32_t a;
    asm("{ .reg .u64 t; cvta.to.shared.u64 t, %1; cvt.u32.u64 %0, t; }" : "=r"(a) : "l"(p));
    return a;
}
__device__ __forceinline__ void mma16816(float* c, const uint32_t* a, const uint32_t* b) {
    asm volatile("mma.sync.aligned.m16n8k16.row.col.f32.bf16.bf16.f32 "
        "{%0,%1,%2,%3}, {%4,%5,%6,%7}, {%8,%9}, {%0,%1,%2,%3};"
        : "+f"(c[0]), "+f"(c[1]), "+f"(c[2]), "+f"(c[3])
        : "r"(a[0]), "r"(a[1]), "r"(a[2]), "r"(a[3]), "r"(b[0]), "r"(b[1]));
}
#define LDSM_X4(r0,r1,r2,r3,addr) \
    asm volatile("ldmatrix.sync.aligned.m8n8.x4.shared.b16 {%0,%1,%2,%3}, [%4];" \
                 : "=r"(r0),"=r"(r1),"=r"(r2),"=r"(r3) : "r"(addr))
#define LDSM_X4T(r0,r1,r2,r3,addr) \
    asm volatile("ldmatrix.sync.aligned.m8n8.x4.trans.shared.b16 {%0,%1,%2,%3}, [%4];" \
                 : "=r"(r0),"=r"(r1),"=r"(r2),"=r"(r3) : "r"(addr))
#define STS_V2(addr,a,b) \
    asm volatile("st.shared.v2.b32 [%0], {%1, %2};" :: "r"(addr), "r"(a), "r"(b) : "memory")
#define CVT_BF16X2(res,a,b) asm("cvt.rn.bf16x2.f32 %0, %1, %2;" : "=r"(res) : "f"(b), "f"(a))
#define EX2F(y,x) asm("ex2.approx.f32 %0, %1;" : "=f"(y) : "f"(x))
#define CP_ASYNC16(dst, src) \
    asm volatile("cp.async.cg.shared.global [%0], [%1], 16;" :: "r"(dst), "l"(src) : "memory")
#define CP_COMMIT() asm volatile("cp.async.commit_group;" ::: "memory")

__device__ __forceinline__ void split4(const float4 v, uint32_t& h0, uint32_t& h1,
                                       uint32_t& l0, uint32_t& l1) {
    CVT_BF16X2(h0, v.x, v.y);
    CVT_BF16X2(h1, v.z, v.w);
    const float r0 = v.x - __uint_as_float(h0 << 16);
    const float r1 = v.y - __uint_as_float(h0 & 0xffff0000u);
    const float r2 = v.z - __uint_as_float(h1 << 16);
    const float r3 = v.w - __uint_as_float(h1 & 0xffff0000u);
    CVT_BF16X2(l0, r0, r1);
    CVT_BF16X2(l1, r2, r3);
}

// ---------------- GEMM via mma.sync (R3-validated, unchanged) ----------------
#define LA 40
#define LB 136
#define AH_OFF 0
#define AL_OFF 10240
#define BH_OFF 20480
#define BL_OFF 29184
#define BUF_BYTES 37888
#define BIAS_OFF  75776
#define GB_SMEM   76288

__global__ void __launch_bounds__(256) gemm_mma(
    const float* __restrict__ X, const float* __restrict__ W,
    const float* __restrict__ bias, float* __restrict__ C, float alpha)
{
    extern __shared__ char smg[];
    const uint32_t sb = smem_u32(smg);
    const int tid = threadIdx.x, wid = tid >> 5, lane = tid & 31;
    const int n0 = blockIdx.x * 128, m0 = blockIdx.y * 128;
    const float* Xb = X + (size_t)blockIdx.z * KDIM * SEQ;
    float*       Cb = C + (size_t)blockIdx.z * EMB * SEQ;
    float* bias_s = (float*)(smg + BIAS_OFF);
    if (tid < 128) bias_s[tid] = bias[m0 + tid];

    const int wm = wid & 3, wn = wid >> 2;
    float acc[2][8][4];
#pragma unroll
    for (int ms = 0; ms < 2; ms++)
#pragma unroll
        for (int nt = 0; nt < 8; nt++)
#pragma unroll
            for (int i = 0; i < 4; i++) acc[ms][nt][i] = 0.f;

    const int arow = lane & 15, ak8 = (lane >> 4) * 8;
    const int bj = lane >> 3, br = lane & 7;
    const int bk = (bj & 1) * 8 + br, bn8 = (bj >> 1) * 8;
    float4 ra[4], rb[4];

#define LOADG(kt) do {                                                         \
    _Pragma("unroll")                                                          \
    for (int i = 0; i < 4; i++) {                                              \
        const int e = i * 256 + tid;                                           \
        const int r = e >> 3, c = e & 7;                                       \
        ra[i] = *(const float4*)&W[(size_t)(m0 + r) * KDIM + (kt) * 32 + c * 4]; \
    }                                                                          \
    _Pragma("unroll")                                                          \
    for (int i = 0; i < 4; i++) {                                              \
        const int e = i * 256 + tid;                                           \
        const int r = e >> 5, c = e & 31;                                      \
        rb[i] = *(const float4*)&Xb[(size_t)((kt) * 32 + r) * SEQ + n0 + c * 4]; \
    }                                                                          \
} while (0)

#define STORES(buf) do {                                                       \
    const uint32_t base = sb + (buf) * BUF_BYTES;                              \
    _Pragma("unroll")                                                          \
    for (int i = 0; i < 4; i++) {                                              \
        const int e = i * 256 + tid;                                           \
        const int r = e >> 3, c = e & 7;                                       \
        uint32_t h0, h1, l0, l1;                                               \
        split4(ra[i], h0, h1, l0, l1);                                         \
        const uint32_t off = (uint32_t)(r * LA + c * 4) * 2;                   \
        STS_V2(base + AH_OFF + off, h0, h1);                                   \
        STS_V2(base + AL_OFF + off, l0, l1);                                   \
    }                                                                          \
    _Pragma("unroll")                                                          \
    for (int i = 0; i < 4; i++) {                                              \
        const int e = i * 256 + tid;                                           \
        const int r = e >> 5, c = e & 31;                                      \
        uint32_t h0, h1, l0, l1;                                               \
        split4(rb[i], h0, h1, l0, l1);                                         \
        const uint32_t off = (uint32_t)(r * LB + c * 4) * 2;                   \
        STS_V2(base + BH_OFF + off, h0, h1);                                   \
        STS_V2(base + BL_OFF + off, l0, l1);                                   \
    }                                                                          \
} while (0)

    LOADG(0);
    STORES(0);
    __syncthreads();

    const int NKT = KDIM / 32;
    for (int kt = 0; kt < NKT; kt++) {
        if (kt + 1 < NKT) LOADG(kt + 1);
        const uint32_t base = sb + (kt & 1) * BUF_BYTES;
#pragma unroll
        for (int ks = 0; ks < 2; ks++) {
            uint32_t aF[2][4], aL[2][4];
#pragma unroll
            for (int ms = 0; ms < 2; ms++) {
                const uint32_t ao = (uint32_t)((wm * 32 + ms * 16 + arow) * LA + ks * 16 + ak8) * 2;
                LDSM_X4(aF[ms][0], aF[ms][1], aF[ms][2], aF[ms][3], base + AH_OFF + ao);
                LDSM_X4(aL[ms][0], aL[ms][1], aL[ms][2], aL[ms][3], base + AL_OFF + ao);
            }
#pragma unroll
            for (int nt16 = 0; nt16 < 4; nt16++) {
                uint32_t bH[4], bL[4];
                const uint32_t bo = (uint32_t)((ks * 16 + bk) * LB + wn * 64 + nt16 * 16 + bn8) * 2;
                LDSM_X4T(bH[0], bH[1], bH[2], bH[3], base + BH_OFF + bo);
                LDSM_X4T(bL[0], bL[1], bL[2], bL[3], base + BL_OFF + bo);
#pragma unroll
                for (int ms = 0; ms < 2; ms++)
#pragma unroll
                    for (int s = 0; s < 2; s++) {
                        float* a4 = acc[ms][nt16 * 2 + s];
                        mma16816(a4, aF[ms], &bH[s * 2]);
                        mma16816(a4, aF[ms], &bL[s * 2]);
                        mma16816(a4, aL[ms], &bH[s * 2]);
                    }
            }
        }
        __syncthreads();
        if (kt + 1 < NKT) { STORES((kt + 1) & 1); __syncthreads(); }
    }

    __syncthreads();
    float* Cs = (float*)smg;
    {
        const int rr = lane >> 2, cc = (lane & 3) * 2;
#pragma unroll
        for (int ms = 0; ms < 2; ms++)
#pragma unroll
            for (int nt = 0; nt < 8; nt++) {
                const int r = wm * 32 + ms * 16 + rr;
                const int c = wn * 64 + nt * 8 + cc;
                Cs[r * 132 + c]           = acc[ms][nt][0];
                Cs[r * 132 + c + 1]       = acc[ms][nt][1];
                Cs[(r + 8) * 132 + c]     = acc[ms][nt][2];
                Cs[(r + 8) * 132 + c + 1] = acc[ms][nt][3];
            }
    }
    __syncthreads();
#pragma unroll
    for (int i = 0; i < 16; i++) {
        const int e = i * 256 + tid;
        const int r = e >> 5, c = e & 31;
        float4 v = *(const float4*)&Cs[r * 132 + c * 4];
        const float bi = bias_s[r];
        v.x = alpha * (v.x + bi); v.y = alpha * (v.y + bi);
        v.z = alpha * (v.z + bi); v.w = alpha * (v.w + bi);
        *(float4*)&Cb[(size_t)(m0 + r) * SEQ + n0 + c * 4] = v;
    }
}

// ---------------- tensorized flash attention, pipelined ---------------------
// CTA: (b, h, 128-q tile); warp w owns q rows [16w,16w+16).
// K and V both staged in natural [dh][key] layout (bf16 hi/lo), double-buffered;
// QK B-frags via trans-LDSM, PV B-frags via plain LDSM (duality). Mask tile
// double-buffered via cp.async. K/V global loads prefetched in registers.
#define PQ 136
#define PK 72
#define KVB 36864            // per KV buffer: KH 0, KL 9216, VH 18432, VL 27648
#define MOFF 73728           // mask buffers: 2 x 64*132*4
#define MBUF 33792
#define AT_SMEM 141312

__global__ void __launch_bounds__(256) attn_mma(
    const float* __restrict__ QP, const float* __restrict__ KP,
    const float* __restrict__ VP, const float* __restrict__ MASK,
    float* __restrict__ OUTP)
{
    extern __shared__ char sma[];
    const uint32_t sb = smem_u32(sma);
    const int tid = threadIdx.x, wid = tid >> 5, lane = tid & 31;
    const int b = blockIdx.z, h = blockIdx.y, q0 = blockIdx.x * 128;

    const float* Qg = QP + ((size_t)b * EMB + h * DH) * SEQ + q0;
    const float* Kg = KP + ((size_t)b * EMB + h * DH) * SEQ;
    const float* Vg = VP + ((size_t)b * EMB + h * DH) * SEQ;
    const float* Mg = MASK + (size_t)b * SEQ * SEQ;
    float*       Og = OUTP + ((size_t)b * EMB + h * DH) * SEQ + q0;

    float4 rk[4], rv[4];

#define LOADG_KV(k0) do {                                                      \
    _Pragma("unroll")                                                          \
    for (int i = 0; i < 4; i++) {                                              \
        const int e = i * 256 + tid;                                           \
        const int r = e >> 4, c = (e & 15) * 4;                                \
        rk[i] = *(const float4*)&Kg[(size_t)r * SEQ + (k0) + c];               \
        rv[i] = *(const float4*)&Vg[(size_t)r * SEQ + (k0) + c];               \
    }                                                                          \
} while (0)

#define STS_KV(buf) do {                                                       \
    const uint32_t base = sb + (buf) * KVB;                                    \
    _Pragma("unroll")                                                          \
    for (int i = 0; i < 4; i++) {                                              \
        const int e = i * 256 + tid;                                           \
        const int r = e >> 4, c = (e & 15) * 4;                                \
        const uint32_t off = (uint32_t)(r * PK + c) * 2;                       \
        uint32_t h0, h1, l0, l1;                                               \
        split4(rk[i], h0, h1, l0, l1);                                         \
        STS_V2(base + off, h0, h1);                                            \
        STS_V2(base + 9216 + off, l0, l1);                                     \
        split4(rv[i], h0, h1, l0, l1);                                         \
        STS_V2(base + 18432 + off, h0, h1);                                    \
        STS_V2(base + 27648 + off, l0, l1);                                    \
    }                                                                          \
} while (0)

#define CP_MASK(k0, buf) do {                                                  \
    const uint32_t mb = sb + MOFF + (buf) * MBUF;                              \
    _Pragma("unroll")                                                          \
    for (int i = 0; i < 8; i++) {                                              \
        const int id = i * 256 + tid;                                          \
        const int r = id >> 5, c32 = id & 31;                                  \
        CP_ASYNC16(mb + (uint32_t)(r * 132 + c32 * 4) * 4,                     \
                   Mg + (size_t)((k0) + r) * SEQ + q0 + c32 * 4);              \
    }                                                                          \
} while (0)

    // ---- stage Q (aliases KV buf0), kick off tile-0 mask + K/V loads ----
    LOADG_KV(0);
    CP_MASK(0, 0);
    CP_COMMIT();
#pragma unroll
    for (int i = 0; i < 8; i++) {
        const int e = i * 256 + tid;
        const int r = e >> 5, c = (e & 31) * 4;
        float4 v = *(const float4*)&Qg[(size_t)r * SEQ + c];
        v.x *= LOG2E; v.y *= LOG2E; v.z *= LOG2E; v.w *= LOG2E;
        uint32_t h0, h1, l0, l1;
        split4(v, h0, h1, l0, l1);
        const uint32_t off = (uint32_t)(r * PQ + c) * 2;
        STS_V2(sb + off, h0, h1);
        STS_V2(sb + 17408 + off, l0, l1);
    }
    __syncthreads();

    const int arow_k = (lane & 7) + ((lane >> 4) << 3);
    const int amcol  = ((lane >> 3) & 1) * 8;
    uint32_t qh[4][4], ql[4][4];
#pragma unroll
    for (int ks = 0; ks < 4; ks++) {
        const uint32_t ao = (uint32_t)((ks * 16 + arow_k) * PQ + wid * 16 + amcol) * 2;
        LDSM_X4T(qh[ks][0], qh[ks][1], qh[ks][2], qh[ks][3], sb + ao);
        LDSM_X4T(ql[ks][0], ql[ks][1], ql[ks][2], ql[ks][3], sb + 17408 + ao);
    }
    __syncthreads();

    STS_KV(0);   // overwrites Q region (frags already in registers)

    // B-frag lane addressing
    const int bj = lane >> 3, br = lane & 7;
    const int bk = (bj & 1) * 8 + br, bn8 = (bj >> 1) * 8;      // trans (QK / K)
    const int bvrow = ((lane >> 4) & 1) * 8 + br;               // plain (PV / V)
    const int bvk8  = ((lane >> 3) & 1) * 8;

    float o[8][4];
#pragma unroll
    for (int d = 0; d < 8; d++)
#pragma unroll
        for (int j = 0; j < 4; j++) o[d][j] = 0.f;
    float lsum0 = 0.f, lsum1 = 0.f;

    const int qr = wid * 16 + (lane >> 2);
    const int krow2 = 2 * (lane & 3);

    const int NT = SEQ / 64;
    for (int kt = 0; kt < NT; kt++) {
        if (kt + 1 < NT) {
            CP_MASK((kt + 1) * 64, (kt + 1) & 1);
            CP_COMMIT();
            LOADG_KV((kt + 1) * 64);
            asm volatile("cp.async.wait_group 1;" ::: "memory");
        } else {
            asm volatile("cp.async.wait_group 0;" ::: "memory");
        }
        __syncthreads();   // KV buf kt ready (STS), mask buf kt ready (cp.async)

        const uint32_t kvb = sb + (kt & 1) * KVB;
        const float* Ms = (const float*)(sma + MOFF + (kt & 1) * MBUF);

        // ---- S accum init = mask * LOG2E (from smem) ----
        float s[8][4];
#pragma unroll
        for (int nt = 0; nt < 8; nt++) {
            const float* mp = Ms + (nt * 8 + krow2) * 132 + qr;
            s[nt][0] = mp[0]   * LOG2E;
            s[nt][1] = mp[132] * LOG2E;
            s[nt][2] = mp[8]   * LOG2E;
            s[nt][3] = mp[140] * LOG2E;
        }
        // ---- QK mma (3-pass) ----
#pragma unroll
        for (int ks = 0; ks < 4; ks++)
#pragma unroll
            for (int np = 0; np < 4; np++) {
                uint32_t kh[4], kl[4];
                const uint32_t bo = (uint32_t)((ks * 16 + bk) * PK + np * 16 + bn8) * 2;
                LDSM_X4T(kh[0], kh[1], kh[2], kh[3], kvb + bo);
                LDSM_X4T(kl[0], kl[1], kl[2], kl[3], kvb + 9216 + bo);
#pragma unroll
                for (int s2 = 0; s2 < 2; s2++) {
                    float* a4 = s[np * 2 + s2];
                    mma16816(a4, qh[ks], &kh[s2 * 2]);
                    mma16816(a4, qh[ks], &kl[s2 * 2]);
                    mma16816(a4, ql[ks], &kh[s2 * 2]);
                }
            }
        // ---- exp2, row sums, pack P into A-frags ----
        float rs0 = 0.f, rs1 = 0.f;
#pragma unroll
        for (int nt = 0; nt < 8; nt++) {
#pragma unroll
            for (int j = 0; j < 4; j++) EX2F(s[nt][j], s[nt][j]);
            rs0 += s[nt][0] + s[nt][1];
            rs1 += s[nt][2] + s[nt][3];
        }
        rs0 += __shfl_xor_sync(0xffffffffu, rs0, 1);
        rs0 += __shfl_xor_sync(0xffffffffu, rs0, 2);
        rs1 += __shfl_xor_sync(0xffffffffu, rs1, 1);
        rs1 += __shfl_xor_sync(0xffffffffu, rs1, 2);
        lsum0 += rs0;
        lsum1 += rs1;

        uint32_t pah[4][4], pal[4][4];
#pragma unroll
        for (int ks = 0; ks < 4; ks++) {
            const float* u = s[ks * 2];
            const float* w = s[ks * 2 + 1];
            CVT_BF16X2(pah[ks][0], u[0], u[1]);
            CVT_BF16X2(pah[ks][1], u[2], u[3]);
            CVT_BF16X2(pah[ks][2], w[0], w[1]);
            CVT_BF16X2(pah[ks][3], w[2], w[3]);
            float t0 = u[0] - __uint_as_float(pah[ks][0] << 16);
            float t1 = u[1] - __uint_as_float(pah[ks][0] & 0xffff0000u);
            float t2 = u[2] - __uint_as_float(pah[ks][1] << 16);
            float t3 = u[3] - __uint_as_float(pah[ks][1] & 0xffff0000u);
            CVT_BF16X2(pal[ks][0], t0, t1);
            CVT_BF16X2(pal[ks][1], t2, t3);
            t0 = w[0] - __uint_as_float(pah[ks][2] << 16);
            t1 = w[1] - __uint_as_float(pah[ks][2] & 0xffff0000u);
            t2 = w[2] - __uint_as_float(pah[ks][3] << 16);
            t3 = w[3] - __uint_as_float(pah[ks][3] & 0xffff0000u);
            CVT_BF16X2(pal[ks][2], t0, t1);
            CVT_BF16X2(pal[ks][3], t2, t3);
        }
        // ---- PV mma: O += P @ V (V natural [dh][key], plain LDSM) ----
#pragma unroll
        for (int ks = 0; ks < 4; ks++)
#pragma unroll
            for (int dp = 0; dp < 4; dp++) {
                uint32_t vh[4], vl[4];
                const uint32_t bo = (uint32_t)((dp * 16 + bvrow) * PK + ks * 16 + bvk8) * 2;
                LDSM_X4(vh[0], vh[1], vh[2], vh[3], kvb + 18432 + bo);
                LDSM_X4(vl[0], vl[1], vl[2], vl[3], kvb + 27648 + bo);
#pragma unroll
                for (int s2 = 0; s2 < 2; s2++) {
                    float* a4 = o[dp * 2 + s2];
                    mma16816(a4, pah[ks], &vh[s2 * 2]);
                    mma16816(a4, pah[ks], &vl[s2 * 2]);
                    mma16816(a4, pal[ks], &vh[s2 * 2]);
                }
            }

        if (kt + 1 < NT) STS_KV((kt + 1) & 1);
    }

    // ---- normalize, transpose via smem, coalesced [E][S] store ----
    const float inv0 = 1.f / lsum0, inv1 = 1.f / lsum1;
    __syncthreads();
    float* Os = (float*)sma;   // [64 dh][132] — aliases KV buf0 (dead)
#pragma unroll
    for (int d = 0; d < 8; d++) {
        const int dc = d * 8 + krow2;
        Os[dc * 132 + qr]           = o[d][0] * inv0;
        Os[(dc + 1) * 132 + qr]     = o[d][1] * inv0;
        Os[dc * 132 + qr + 8]       = o[d][2] * inv1;
        Os[(dc + 1) * 132 + qr + 8] = o[d][3] * inv1;
    }
    __syncthreads();
#pragma unroll
    for (int i = 0; i < 8; i++) {
        const int e = i * 256 + tid;
        const int r = e >> 5, c = (e & 31) * 4;
        *(float4*)&Og[(size_t)r * SEQ + c] = *(const float4*)&Os[r * 132 + c];
    }
}

// ---------------------------------------------------------------------------
extern "C" void kernel_launch(void* const* d_in, const int* in_sizes, int n_in,
                              void* d_out, int out_size)
{
    const float* q   = (const float*)d_in[0];
    const float* k   = (const float*)d_in[1];
    const float* v   = (const float*)d_in[2];
    const float* msk = (const float*)d_in[3];
    const float* Wq  = (const float*)d_in[4];
    const float* bq  = (const float*)d_in[5];
    const float* Wk  = (const float*)d_in[6];
    const float* bk  = (const float*)d_in[7];
    const float* Wv  = (const float*)d_in[8];
    const float* bv  = (const float*)d_in[9];
    const float* Wo  = (const float*)d_in[10];
    const float* bo  = (const float*)d_in[11];
    float* out = (float*)d_out;

    void *pqp, *pkp, *pvp, *pat;
    cudaGetSymbolAddress(&pqp, g_qp);
    cudaGetSymbolAddress(&pkp, g_kp);
    cudaGetSymbolAddress(&pvp, g_vp);
    cudaGetSymbolAddress(&pat, g_at);

    cudaFuncSetAttribute(gemm_mma, cudaFuncAttributeMaxDynamicSharedMemorySize, GB_SMEM);
    cudaFuncSetAttribute(attn_mma, cudaFuncAttributeMaxDynamicSharedMemorySize, AT_SMEM);

    dim3 gg(SEQ / 128, EMB / 128, BATCH);
    gemm_mma<<<gg, 256, GB_SMEM>>>(q, Wq, bq, (float*)pqp, 0.125f);
    gemm_mma<<<gg, 256, GB_SMEM>>>(k, Wk, bk, (float*)pkp, 1.0f);
    gemm_mma<<<gg, 256, GB_SMEM>>>(v, Wv, bv, (float*)pvp, 1.0f);

    dim3 ga(SEQ / 128, NH, BATCH);
    attn_mma<<<ga, 256, AT_SMEM>>>(
        (const float*)pqp, (const float*)pkp, (const float*)pvp, msk, (float*)pat);

    gemm_mma<<<gg, 256, GB_SMEM>>>((const float*)pat, Wo, bo, out, 1.0f);
}

// round 8
// speedup vs baseline: 1.9707x; 1.0151x over previous
#include <cuda_runtime.h>
#include <cstdint>

#define BATCH 2
#define EMB   1024
#define SEQ   2048
#define NH    16
#define DH    64
#define KDIM  1024
#define LOG2E 1.4426950408889634f
typedef unsigned short ushort_t;

// ---------------- scratch ----------------------------------------------------
__device__ ushort_t g_wh[4][(size_t)KDIM * EMB];          // Wq,Wk,Wv,Wo hi
__device__ ushort_t g_wl[4][(size_t)KDIM * EMB];          // lo
__device__ ushort_t g_xh[3][(size_t)BATCH * EMB * SEQ];   // q,k,v inputs hi
__device__ ushort_t g_xl[3][(size_t)BATCH * EMB * SEQ];
__device__ ushort_t g_ph[3][(size_t)BATCH * EMB * SEQ];   // Q,K,V proj hi
__device__ ushort_t g_pl[3][(size_t)BATCH * EMB * SEQ];
__device__ ushort_t g_ath[(size_t)BATCH * EMB * SEQ];     // attn out hi
__device__ ushort_t g_atl[(size_t)BATCH * EMB * SEQ];

// ---------------- helpers ----------------------------------------------------
__device__ __forceinline__ uint32_t smem_u32(const void* p) {
    uint32_t a;
    asm("{ .reg .u64 t; cvta.to.shared.u64 t, %1; cvt.u32.u64 %0, t; }" : "=r"(a) : "l"(p));
    return a;
}
__device__ __forceinline__ void mma16816(float* c, const uint32_t* a, const uint32_t* b) {
    asm volatile("mma.sync.aligned.m16n8k16.row.col.f32.bf16.bf16.f32 "
        "{%0,%1,%2,%3}, {%4,%5,%6,%7}, {%8,%9}, {%0,%1,%2,%3};"
        : "+f"(c[0]), "+f"(c[1]), "+f"(c[2]), "+f"(c[3])
        : "r"(a[0]), "r"(a[1]), "r"(a[2]), "r"(a[3]), "r"(b[0]), "r"(b[1]));
}
#define LDSM_X4(r0,r1,r2,r3,addr) \
    asm volatile("ldmatrix.sync.aligned.m8n8.x4.shared.b16 {%0,%1,%2,%3}, [%4];" \
                 : "=r"(r0),"=r"(r1),"=r"(r2),"=r"(r3) : "r"(addr))
#define LDSM_X4T(r0,r1,r2,r3,addr) \
    asm volatile("ldmatrix.sync.aligned.m8n8.x4.trans.shared.b16 {%0,%1,%2,%3}, [%4];" \
                 : "=r"(r0),"=r"(r1),"=r"(r2),"=r"(r3) : "r"(addr))
#define CVT_BF16X2(res,a,b) asm("cvt.rn.bf16x2.f32 %0, %1, %2;" : "=r"(res) : "f"(b), "f"(a))
#define EX2F(y,x) asm("ex2.approx.f32 %0, %1;" : "=f"(y) : "f"(x))
#define CP_ASYNC16(dst, src) \
    asm volatile("cp.async.cg.shared.global [%0], [%1], 16;" :: "r"(dst), "l"(src) : "memory")
#define CP_COMMIT() asm volatile("cp.async.commit_group;" ::: "memory")
#define CP_WAIT(n) asm volatile("cp.async.wait_group %0;" :: "n"(n) : "memory")

__device__ __forceinline__ void split4(const float4 v, uint32_t& h0, uint32_t& h1,
                                       uint32_t& l0, uint32_t& l1) {
    CVT_BF16X2(h0, v.x, v.y);
    CVT_BF16X2(h1, v.z, v.w);
    const float r0 = v.x - __uint_as_float(h0 << 16);
    const float r1 = v.y - __uint_as_float(h0 & 0xffff0000u);
    const float r2 = v.z - __uint_as_float(h1 << 16);
    const float r3 = v.w - __uint_as_float(h1 & 0xffff0000u);
    CVT_BF16X2(l0, r0, r1);
    CVT_BF16X2(l1, r2, r3);
}

// ---------------- one-time f32 -> bf16 hi/lo convert -------------------------
__global__ void __launch_bounds__(256) to_hilo(
    const float* __restrict__ in, ushort_t* __restrict__ hi, ushort_t* __restrict__ lo)
{
    const size_t i = ((size_t)blockIdx.x * 256 + threadIdx.x) * 4;
    const float4 v = *(const float4*)&in[i];
    uint32_t h0, h1, l0, l1;
    split4(v, h0, h1, l0, l1);
    *(uint2*)&hi[i] = make_uint2(h0, h1);
    *(uint2*)&lo[i] = make_uint2(l0, l1);
}

// ---------------- GEMM, pure bf16 cp.async path ------------------------------
// C[b] = alpha * (W @ X[b] + bias). A = W [M][K] hi/lo, B = X [K][N] hi/lo.
// 128x128 tile, BK=32, 8 warps. Output f32 (Cf) or hi/lo (Ch/Cl).
#define LAH 56      // A smem pitch halves (112B: 16B-aligned, conflict-free)
#define LBH 136     // B smem pitch halves (272B)
#define G_AH 0
#define G_AL 14336
#define G_BH 28672
#define G_BL 37376
#define G_BUF 46080
#define G_BIAS 92160
#define GB_SMEM 92672

__global__ void __launch_bounds__(256, 2) gemm_bf16(
    const ushort_t* __restrict__ Ah, const ushort_t* __restrict__ Al,
    const ushort_t* __restrict__ Bh, const ushort_t* __restrict__ Bl,
    const float* __restrict__ bias, float* __restrict__ Cf,
    ushort_t* __restrict__ Ch, ushort_t* __restrict__ Cl, float alpha)
{
    extern __shared__ char smg[];
    const uint32_t sb = smem_u32(smg);
    const int tid = threadIdx.x, wid = tid >> 5, lane = tid & 31;
    const int n0 = blockIdx.x * 128, m0 = blockIdx.y * 128;
    const size_t boff = (size_t)blockIdx.z * KDIM * SEQ;
    const size_t coff = (size_t)blockIdx.z * EMB * SEQ;
    float* bias_s = (float*)(smg + G_BIAS);
    if (tid < 128) bias_s[tid] = bias[m0 + tid];

    const int wm = wid & 3, wn = wid >> 2;
    float acc[2][8][4];
#pragma unroll
    for (int ms = 0; ms < 2; ms++)
#pragma unroll
        for (int nt = 0; nt < 8; nt++)
#pragma unroll
            for (int i = 0; i < 4; i++) acc[ms][nt][i] = 0.f;

    const int arow = lane & 15, ak8 = (lane >> 4) * 8;
    const int bj = lane >> 3, br = lane & 7;
    const int bk = (bj & 1) * 8 + br, bn8 = (bj >> 1) * 8;

#define G_CP(kt, buf) do {                                                     \
    const uint32_t base = sb + (buf) * G_BUF;                                  \
    _Pragma("unroll")                                                          \
    for (int i = 0; i < 2; i++) {                                              \
        const int id = i * 256 + tid;                                          \
        const int r = id >> 2, c = id & 3;                                     \
        const size_t so = (size_t)(m0 + r) * KDIM + (kt) * 32 + c * 8;         \
        const uint32_t doff = (uint32_t)(r * 112 + c * 16);                    \
        CP_ASYNC16(base + G_AH + doff, Ah + so);                               \
        CP_ASYNC16(base + G_AL + doff, Al + so);                               \
    }                                                                          \
    _Pragma("unroll")                                                          \
    for (int i = 0; i < 2; i++) {                                              \
        const int id = i * 256 + tid;                                          \
        const int r = id >> 4, c = id & 15;                                    \
        const size_t so = boff + (size_t)((kt) * 32 + r) * SEQ + n0 + c * 8;   \
        const uint32_t doff = (uint32_t)(r * 272 + c * 16);                    \
        CP_ASYNC16(base + G_BH + doff, Bh + so);                               \
        CP_ASYNC16(base + G_BL + doff, Bl + so);                               \
    }                                                                          \
} while (0)

    G_CP(0, 0);
    CP_COMMIT();

    const int NKT = KDIM / 32;
    for (int kt = 0; kt < NKT; kt++) {
        __syncthreads();
        if (kt + 1 < NKT) { G_CP(kt + 1, (kt + 1) & 1); CP_COMMIT(); CP_WAIT(1); }
        else CP_WAIT(0);
        __syncthreads();

        const uint32_t base = sb + (kt & 1) * G_BUF;
#pragma unroll
        for (int ks = 0; ks < 2; ks++) {
            uint32_t aF[2][4], aL[2][4];
#pragma unroll
            for (int ms = 0; ms < 2; ms++) {
                const uint32_t ao = (uint32_t)((wm * 32 + ms * 16 + arow) * LAH + ks * 16 + ak8) * 2;
                LDSM_X4(aF[ms][0], aF[ms][1], aF[ms][2], aF[ms][3], base + G_AH + ao);
                LDSM_X4(aL[ms][0], aL[ms][1], aL[ms][2], aL[ms][3], base + G_AL + ao);
            }
#pragma unroll
            for (int nt16 = 0; nt16 < 4; nt16++) {
                uint32_t bH[4], bL[4];
                const uint32_t bo = (uint32_t)((ks * 16 + bk) * LBH + wn * 64 + nt16 * 16 + bn8) * 2;
                LDSM_X4T(bH[0], bH[1], bH[2], bH[3], base + G_BH + bo);
                LDSM_X4T(bL[0], bL[1], bL[2], bL[3], base + G_BL + bo);
#pragma unroll
                for (int ms = 0; ms < 2; ms++)
#pragma unroll
                    for (int s = 0; s < 2; s++) {
                        float* a4 = acc[ms][nt16 * 2 + s];
                        mma16816(a4, aF[ms], &bH[s * 2]);
                        mma16816(a4, aF[ms], &bL[s * 2]);
                        mma16816(a4, aL[ms], &bH[s * 2]);
                    }
            }
        }
    }

    // epilogue: regs -> smem transpose -> coalesced stores
    __syncthreads();
    float* Cs = (float*)smg;
    {
        const int rr = lane >> 2, cc = (lane & 3) * 2;
#pragma unroll
        for (int ms = 0; ms < 2; ms++)
#pragma unroll
            for (int nt = 0; nt < 8; nt++) {
                const int r = wm * 32 + ms * 16 + rr;
                const int c = wn * 64 + nt * 8 + cc;
                Cs[r * 132 + c]           = acc[ms][nt][0];
                Cs[r * 132 + c + 1]       = acc[ms][nt][1];
                Cs[(r + 8) * 132 + c]     = acc[ms][nt][2];
                Cs[(r + 8) * 132 + c + 1] = acc[ms][nt][3];
            }
    }
    __syncthreads();
#pragma unroll
    for (int i = 0; i < 16; i++) {
        const int e = i * 256 + tid;
        const int r = e >> 5, c4 = (e & 31) * 4;
        float4 v = *(const float4*)&Cs[r * 132 + c4];
        const float bi = bias_s[r];
        v.x = alpha * (v.x + bi); v.y = alpha * (v.y + bi);
        v.z = alpha * (v.z + bi); v.w = alpha * (v.w + bi);
        const size_t go = coff + (size_t)(m0 + r) * SEQ + n0 + c4;
        if (Cf) {
            *(float4*)&Cf[go] = v;
        } else {
            uint32_t h0, h1, l0, l1;
            split4(v, h0, h1, l0, l1);
            *(uint2*)&Ch[go] = make_uint2(h0, h1);
            *(uint2*)&Cl[go] = make_uint2(l0, l1);
        }
    }
}

// ---------------- tensorized flash attention, pure cp.async staging ----------
#define PQ 136
#define PK 72
#define KVB 36864            // per KV buffer: KH 0, KL 9216, VH 18432, VL 27648
#define MOFF 73728           // mask buffers: 2 x 64*132*4
#define MBUF 33792
#define AT_SMEM 141312

__global__ void __launch_bounds__(256) attn_mma(
    const ushort_t* __restrict__ Qh, const ushort_t* __restrict__ Ql,
    const ushort_t* __restrict__ Kh, const ushort_t* __restrict__ Kl,
    const ushort_t* __restrict__ Vh, const ushort_t* __restrict__ Vl,
    const float* __restrict__ MASK,
    ushort_t* __restrict__ Oh, ushort_t* __restrict__ Ol)
{
    extern __shared__ char sma[];
    const uint32_t sb = smem_u32(sma);
    const int tid = threadIdx.x, wid = tid >> 5, lane = tid & 31;
    const int b = blockIdx.z, h = blockIdx.y, q0 = blockIdx.x * 128;

    const size_t hoff = ((size_t)b * EMB + h * DH) * SEQ;
    const float* Mg = MASK + (size_t)b * SEQ * SEQ;

#define A_CPKV(k0, buf) do {                                                   \
    const uint32_t base = sb + (buf) * KVB;                                    \
    _Pragma("unroll")                                                          \
    for (int i = 0; i < 2; i++) {                                              \
        const int id = i * 256 + tid;                                          \
        const int r = id >> 3, c = id & 7;                                     \
        const size_t so = hoff + (size_t)r * SEQ + (k0) + c * 8;               \
        const uint32_t doff = (uint32_t)(r * 144 + c * 16);                    \
        CP_ASYNC16(base +         doff, Kh + so);                              \
        CP_ASYNC16(base +  9216 + doff, Kl + so);                              \
        CP_ASYNC16(base + 18432 + doff, Vh + so);                              \
        CP_ASYNC16(base + 27648 + doff, Vl + so);                              \
    }                                                                          \
} while (0)

#define A_CPMASK(k0, buf) do {                                                 \
    const uint32_t mb = sb + MOFF + (buf) * MBUF;                              \
    _Pragma("unroll")                                                          \
    for (int i = 0; i < 8; i++) {                                              \
        const int id = i * 256 + tid;                                          \
        const int r = id >> 5, c32 = id & 31;                                  \
        CP_ASYNC16(mb + (uint32_t)(r * 132 + c32 * 4) * 4,                     \
                   Mg + (size_t)((k0) + r) * SEQ + q0 + c32 * 4);              \
    }                                                                          \
} while (0)

    // ---- preamble: Q (into KV buf1 area) + mask0 as group A; KV0 as group B --
    {
        const uint32_t qb = sb + KVB;   // Q staging aliases KV buf1
#pragma unroll
        for (int i = 0; i < 4; i++) {
            const int id = i * 256 + tid;
            const int r = id >> 4, c = id & 15;
            const size_t so = hoff + (size_t)r * SEQ + q0 + c * 8;
            const uint32_t doff = (uint32_t)(r * 272 + c * 16);
            CP_ASYNC16(qb + doff, Qh + so);
            CP_ASYNC16(qb + 17408 + doff, Ql + so);
        }
    }
    A_CPMASK(0, 0);
    CP_COMMIT();
    A_CPKV(0, 0);
    CP_COMMIT();
    CP_WAIT(1);          // Q + mask0 arrived
    __syncthreads();

    const int arow_k = (lane & 7) + ((lane >> 4) << 3);
    const int amcol  = ((lane >> 3) & 1) * 8;
    uint32_t qfh[4][4], qfl[4][4];
#pragma unroll
    for (int ks = 0; ks < 4; ks++) {
        const uint32_t ao = (uint32_t)((ks * 16 + arow_k) * PQ + wid * 16 + amcol) * 2;
        LDSM_X4T(qfh[ks][0], qfh[ks][1], qfh[ks][2], qfh[ks][3], sb + KVB + ao);
        LDSM_X4T(qfl[ks][0], qfl[ks][1], qfl[ks][2], qfl[ks][3], sb + KVB + 17408 + ao);
    }
    __syncthreads();     // Q region free for KV buf1 cp (issued in iter 0)

    const int bj = lane >> 3, br = lane & 7;
    const int bk = (bj & 1) * 8 + br, bn8 = (bj >> 1) * 8;      // trans (K)
    const int bvrow = ((lane >> 4) & 1) * 8 + br;               // plain (V)
    const int bvk8  = ((lane >> 3) & 1) * 8;

    float o[8][4];
#pragma unroll
    for (int d = 0; d < 8; d++)
#pragma unroll
        for (int j = 0; j < 4; j++) o[d][j] = 0.f;
    float lsum0 = 0.f, lsum1 = 0.f;

    const int qr = wid * 16 + (lane >> 2);
    const int krow2 = 2 * (lane & 3);

    const int NT = SEQ / 64;
    for (int kt = 0; kt < NT; kt++) {
        __syncthreads();   // all warps done reading buf[(kt+1)&1] (iter kt-1)
        if (kt + 1 < NT) {
            A_CPKV((kt + 1) * 64, (kt + 1) & 1);
            A_CPMASK((kt + 1) * 64, (kt + 1) & 1);
            CP_COMMIT();
            CP_WAIT(1);
        } else {
            CP_WAIT(0);
        }
        __syncthreads();   // buf kt ready for all warps

        const uint32_t kvb = sb + (kt & 1) * KVB;
        const float* Ms = (const float*)(sma + MOFF + (kt & 1) * MBUF);

        // ---- S accum init = mask * LOG2E ----
        float s[8][4];
#pragma unroll
        for (int nt = 0; nt < 8; nt++) {
            const float* mp = Ms + (nt * 8 + krow2) * 132 + qr;
            s[nt][0] = mp[0]   * LOG2E;
            s[nt][1] = mp[132] * LOG2E;
            s[nt][2] = mp[8]   * LOG2E;
            s[nt][3] = mp[140] * LOG2E;
        }
        // ---- QK mma (3-pass) ----
#pragma unroll
        for (int ks = 0; ks < 4; ks++)
#pragma unroll
            for (int np = 0; np < 4; np++) {
                uint32_t kh[4], kl[4];
                const uint32_t bo = (uint32_t)((ks * 16 + bk) * PK + np * 16 + bn8) * 2;
                LDSM_X4T(kh[0], kh[1], kh[2], kh[3], kvb + bo);
                LDSM_X4T(kl[0], kl[1], kl[2], kl[3], kvb + 9216 + bo);
#pragma unroll
                for (int s2 = 0; s2 < 2; s2++) {
                    float* a4 = s[np * 2 + s2];
                    mma16816(a4, qfh[ks], &kh[s2 * 2]);
                    mma16816(a4, qfh[ks], &kl[s2 * 2]);
                    mma16816(a4, qfl[ks], &kh[s2 * 2]);
                }
            }
        // ---- exp2, row sums, pack P ----
        float rs0 = 0.f, rs1 = 0.f;
#pragma unroll
        for (int nt = 0; nt < 8; nt++) {
#pragma unroll
            for (int j = 0; j < 4; j++) EX2F(s[nt][j], s[nt][j]);
            rs0 += s[nt][0] + s[nt][1];
            rs1 += s[nt][2] + s[nt][3];
        }
        rs0 += __shfl_xor_sync(0xffffffffu, rs0, 1);
        rs0 += __shfl_xor_sync(0xffffffffu, rs0, 2);
        rs1 += __shfl_xor_sync(0xffffffffu, rs1, 1);
        rs1 += __shfl_xor_sync(0xffffffffu, rs1, 2);
        lsum0 += rs0;
        lsum1 += rs1;

        uint32_t pah[4][4], pal[4][4];
#pragma unroll
        for (int ks = 0; ks < 4; ks++) {
            const float* u = s[ks * 2];
            const float* w = s[ks * 2 + 1];
            CVT_BF16X2(pah[ks][0], u[0], u[1]);
            CVT_BF16X2(pah[ks][1], u[2], u[3]);
            CVT_BF16X2(pah[ks][2], w[0], w[1]);
            CVT_BF16X2(pah[ks][3], w[2], w[3]);
            float t0 = u[0] - __uint_as_float(pah[ks][0] << 16);
            float t1 = u[1] - __uint_as_float(pah[ks][0] & 0xffff0000u);
            float t2 = u[2] - __uint_as_float(pah[ks][1] << 16);
            float t3 = u[3] - __uint_as_float(pah[ks][1] & 0xffff0000u);
            CVT_BF16X2(pal[ks][0], t0, t1);
            CVT_BF16X2(pal[ks][1], t2, t3);
            t0 = w[0] - __uint_as_float(pah[ks][2] << 16);
            t1 = w[1] - __uint_as_float(pah[ks][2] & 0xffff0000u);
            t2 = w[2] - __uint_as_float(pah[ks][3] << 16);
            t3 = w[3] - __uint_as_float(pah[ks][3] & 0xffff0000u);
            CVT_BF16X2(pal[ks][2], t0, t1);
            CVT_BF16X2(pal[ks][3], t2, t3);
        }
        // ---- PV mma: O += P @ V (V natural [dh][key], plain LDSM) ----
#pragma unroll
        for (int ks = 0; ks < 4; ks++)
#pragma unroll
            for (int dp = 0; dp < 4; dp++) {
                uint32_t vh[4], vl[4];
                const uint32_t bo = (uint32_t)((dp * 16 + bvrow) * PK + ks * 16 + bvk8) * 2;
                LDSM_X4(vh[0], vh[1], vh[2], vh[3], kvb + 18432 + bo);
                LDSM_X4(vl[0], vl[1], vl[2], vl[3], kvb + 27648 + bo);
#pragma unroll
                for (int s2 = 0; s2 < 2; s2++) {
                    float* a4 = o[dp * 2 + s2];
                    mma16816(a4, pah[ks], &vh[s2 * 2]);
                    mma16816(a4, pah[ks], &vl[s2 * 2]);
                    mma16816(a4, pal[ks], &vh[s2 * 2]);
                }
            }
    }

    // ---- normalize, transpose via smem, hi/lo coalesced store ----
    const float inv0 = 1.f / lsum0, inv1 = 1.f / lsum1;
    __syncthreads();
    float* Os = (float*)sma;   // [64 dh][132] — aliases KV bufs (dead)
#pragma unroll
    for (int d = 0; d < 8; d++) {
        const int dc = d * 8 + krow2;
        Os[dc * 132 + qr]           = o[d][0] * inv0;
        Os[(dc + 1) * 132 + qr]     = o[d][1] * inv0;
        Os[dc * 132 + qr + 8]       = o[d][2] * inv1;
        Os[(dc + 1) * 132 + qr + 8] = o[d][3] * inv1;
    }
    __syncthreads();
#pragma unroll
    for (int i = 0; i < 8; i++) {
        const int e = i * 256 + tid;
        const int r = e >> 5, c4 = (e & 31) * 4;
        const float4 v = *(const float4*)&Os[r * 132 + c4];
        uint32_t h0, h1, l0, l1;
        split4(v, h0, h1, l0, l1);
        const size_t go = hoff + (size_t)r * SEQ + q0 + c4;
        *(uint2*)&Oh[go] = make_uint2(h0, h1);
        *(uint2*)&Ol[go] = make_uint2(l0, l1);
    }
}

// ---------------------------------------------------------------------------
extern "C" void kernel_launch(void* const* d_in, const int* in_sizes, int n_in,
                              void* d_out, int out_size)
{
    const float* q   = (const float*)d_in[0];
    const float* k   = (const float*)d_in[1];
    const float* v   = (const float*)d_in[2];
    const float* msk = (const float*)d_in[3];
    const float* Wq  = (const float*)d_in[4];
    const float* bq  = (const float*)d_in[5];
    const float* Wk  = (const float*)d_in[6];
    const float* bk  = (const float*)d_in[7];
    const float* Wv  = (const float*)d_in[8];
    const float* bv  = (const float*)d_in[9];
    const float* Wo  = (const float*)d_in[10];
    const float* bo  = (const float*)d_in[11];
    float* out = (float*)d_out;

    void *pwh, *pwl, *pxh, *pxl, *pph, *ppl, *path, *patl;
    cudaGetSymbolAddress(&pwh, g_wh);
    cudaGetSymbolAddress(&pwl, g_wl);
    cudaGetSymbolAddress(&pxh, g_xh);
    cudaGetSymbolAddress(&pxl, g_xl);
    cudaGetSymbolAddress(&pph, g_ph);
    cudaGetSymbolAddress(&ppl, g_pl);
    cudaGetSymbolAddress(&path, g_ath);
    cudaGetSymbolAddress(&patl, g_atl);

    ushort_t* wh = (ushort_t*)pwh;  ushort_t* wl = (ushort_t*)pwl;
    ushort_t* xh = (ushort_t*)pxh;  ushort_t* xl = (ushort_t*)pxl;
    ushort_t* ph = (ushort_t*)pph;  ushort_t* pl = (ushort_t*)ppl;
    ushort_t* ath = (ushort_t*)path; ushort_t* atl = (ushort_t*)patl;

    const size_t WSZ = (size_t)KDIM * EMB;          // 1M
    const size_t XSZ = (size_t)BATCH * EMB * SEQ;   // 4M

    cudaFuncSetAttribute(gemm_bf16, cudaFuncAttributeMaxDynamicSharedMemorySize, GB_SMEM);
    cudaFuncSetAttribute(attn_mma, cudaFuncAttributeMaxDynamicSharedMemorySize, AT_SMEM);

    // 1. one-time converts
    to_hilo<<<(int)(WSZ / 1024), 256>>>(Wq, wh + 0 * WSZ, wl + 0 * WSZ);
    to_hilo<<<(int)(WSZ / 1024), 256>>>(Wk, wh + 1 * WSZ, wl + 1 * WSZ);
    to_hilo<<<(int)(WSZ / 1024), 256>>>(Wv, wh + 2 * WSZ, wl + 2 * WSZ);
    to_hilo<<<(int)(WSZ / 1024), 256>>>(Wo, wh + 3 * WSZ, wl + 3 * WSZ);
    to_hilo<<<(int)(XSZ / 1024), 256>>>(q, xh + 0 * XSZ, xl + 0 * XSZ);
    to_hilo<<<(int)(XSZ / 1024), 256>>>(k, xh + 1 * XSZ, xl + 1 * XSZ);
    to_hilo<<<(int)(XSZ / 1024), 256>>>(v, xh + 2 * XSZ, xl + 2 * XSZ);

    // 2. projections (hi/lo outputs); LOG2E folded into Q alpha
    dim3 gg(SEQ / 128, EMB / 128, BATCH);
    gemm_bf16<<<gg, 256, GB_SMEM>>>(wh + 0 * WSZ, wl + 0 * WSZ, xh + 0 * XSZ, xl + 0 * XSZ,
                                    bq, nullptr, ph + 0 * XSZ, pl + 0 * XSZ, 0.125f * LOG2E);
    gemm_bf16<<<gg, 256, GB_SMEM>>>(wh + 1 * WSZ, wl + 1 * WSZ, xh + 1 * XSZ, xl + 1 * XSZ,
                                    bk, nullptr, ph + 1 * XSZ, pl + 1 * XSZ, 1.0f);
    gemm_bf16<<<gg, 256, GB_SMEM>>>(wh + 2 * WSZ, wl + 2 * WSZ, xh + 2 * XSZ, xl + 2 * XSZ,
                                    bv, nullptr, ph + 2 * XSZ, pl + 2 * XSZ, 1.0f);

    // 3. attention (hi/lo in, hi/lo out)
    dim3 ga(SEQ / 128, NH, BATCH);
    attn_mma<<<ga, 256, AT_SMEM>>>(ph + 0 * XSZ, pl + 0 * XSZ,
                                   ph + 1 * XSZ, pl + 1 * XSZ,
                                   ph + 2 * XSZ, pl + 2 * XSZ,
                                   msk, ath, atl);

    // 4. output projection (f32 out)
    gemm_bf16<<<gg, 256, GB_SMEM>>>(wh + 3 * WSZ, wl + 3 * WSZ, ath, atl,
                                    bo, out, nullptr, nullptr, 1.0f);
}

// round 9
// speedup vs baseline: 2.0759x; 1.0534x over previous
#include <cuda_runtime.h>
#include <cstdint>

#define BATCH 2
#define EMB   1024
#define SEQ   2048
#define NH    16
#define DH    64
#define KDIM  1024
#define LOG2E 1.4426950408889634f
typedef unsigned short ushort_t;

#define WSZ ((size_t)KDIM * EMB)
#define XSZ ((size_t)BATCH * EMB * SEQ)
#define ESZ ((size_t)EMB * SEQ)

// ---------------- scratch ----------------------------------------------------
__device__ ushort_t g_wh[4 * WSZ];
__device__ ushort_t g_wl[4 * WSZ];
__device__ ushort_t g_xh[3 * XSZ];
__device__ ushort_t g_xl[3 * XSZ];
__device__ ushort_t g_ph[3 * XSZ];
__device__ ushort_t g_pl[3 * XSZ];
__device__ ushort_t g_ath[XSZ];
__device__ ushort_t g_atl[XSZ];

// ---------------- helpers ----------------------------------------------------
__device__ __forceinline__ uint32_t smem_u32(const void* p) {
    uint32_t a;
    asm("{ .reg .u64 t; cvta.to.shared.u64 t, %1; cvt.u32.u64 %0, t; }" : "=r"(a) : "l"(p));
    return a;
}
__device__ __forceinline__ void mma16816(float* c, const uint32_t* a, const uint32_t* b) {
    asm volatile("mma.sync.aligned.m16n8k16.row.col.f32.bf16.bf16.f32 "
        "{%0,%1,%2,%3}, {%4,%5,%6,%7}, {%8,%9}, {%0,%1,%2,%3};"
        : "+f"(c[0]), "+f"(c[1]), "+f"(c[2]), "+f"(c[3])
        : "r"(a[0]), "r"(a[1]), "r"(a[2]), "r"(a[3]), "r"(b[0]), "r"(b[1]));
}
#define LDSM_X4(r0,r1,r2,r3,addr) \
    asm volatile("ldmatrix.sync.aligned.m8n8.x4.shared.b16 {%0,%1,%2,%3}, [%4];" \
                 : "=r"(r0),"=r"(r1),"=r"(r2),"=r"(r3) : "r"(addr))
#define LDSM_X4T(r0,r1,r2,r3,addr) \
    asm volatile("ldmatrix.sync.aligned.m8n8.x4.trans.shared.b16 {%0,%1,%2,%3}, [%4];" \
                 : "=r"(r0),"=r"(r1),"=r"(r2),"=r"(r3) : "r"(addr))
#define CVT_BF16X2(res,a,b) asm("cvt.rn.bf16x2.f32 %0, %1, %2;" : "=r"(res) : "f"(b), "f"(a))
#define EX2F(y,x) asm("ex2.approx.f32 %0, %1;" : "=f"(y) : "f"(x))
#define CP_ASYNC16(dst, src) \
    asm volatile("cp.async.cg.shared.global [%0], [%1], 16;" :: "r"(dst), "l"(src) : "memory")
#define CP_COMMIT() asm volatile("cp.async.commit_group;" ::: "memory")
#define CP_WAIT(n) asm volatile("cp.async.wait_group %0;" :: "n"(n) : "memory")

__device__ __forceinline__ void split4(const float4 v, uint32_t& h0, uint32_t& h1,
                                       uint32_t& l0, uint32_t& l1) {
    CVT_BF16X2(h0, v.x, v.y);
    CVT_BF16X2(h1, v.z, v.w);
    const float r0 = v.x - __uint_as_float(h0 << 16);
    const float r1 = v.y - __uint_as_float(h0 & 0xffff0000u);
    const float r2 = v.z - __uint_as_float(h1 << 16);
    const float r3 = v.w - __uint_as_float(h1 & 0xffff0000u);
    CVT_BF16X2(l0, r0, r1);
    CVT_BF16X2(l1, r2, r3);
}

// ---------------- merged converts --------------------------------------------
__global__ void __launch_bounds__(256) to_hilo_w(
    const float* __restrict__ w0, const float* __restrict__ w1,
    const float* __restrict__ w2, const float* __restrict__ w3,
    ushort_t* __restrict__ hi, ushort_t* __restrict__ lo)
{
    const int g = blockIdx.y;
    const float* src = g == 0 ? w0 : (g == 1 ? w1 : (g == 2 ? w2 : w3));
    const size_t i = ((size_t)blockIdx.x * 256 + threadIdx.x) * 4;
    const float4 v = *(const float4*)&src[i];
    uint32_t h0, h1, l0, l1;
    split4(v, h0, h1, l0, l1);
    *(uint2*)&hi[g * WSZ + i] = make_uint2(h0, h1);
    *(uint2*)&lo[g * WSZ + i] = make_uint2(l0, l1);
}
__global__ void __launch_bounds__(256) to_hilo_x(
    const float* __restrict__ x0, const float* __restrict__ x1,
    const float* __restrict__ x2,
    ushort_t* __restrict__ hi, ushort_t* __restrict__ lo)
{
    const int g = blockIdx.y;
    const float* src = g == 0 ? x0 : (g == 1 ? x1 : x2);
    const size_t i = ((size_t)blockIdx.x * 256 + threadIdx.x) * 4;
    const float4 v = *(const float4*)&src[i];
    uint32_t h0, h1, l0, l1;
    split4(v, h0, h1, l0, l1);
    *(uint2*)&hi[g * XSZ + i] = make_uint2(h0, h1);
    *(uint2*)&lo[g * XSZ + i] = make_uint2(l0, l1);
}

// ---------------- GEMM body (pure bf16 cp.async path) -------------------------
#define LAH 56
#define LBH 136
#define G_AH 0
#define G_AL 14336
#define G_BH 28672
#define G_BL 37376
#define G_BUF 46080
#define G_BIAS 92160
#define GB_SMEM 92672

__device__ __forceinline__ void gemm_body(
    const ushort_t* __restrict__ Ah, const ushort_t* __restrict__ Al,
    const ushort_t* __restrict__ Bh, const ushort_t* __restrict__ Bl,
    const float* __restrict__ bias, float* __restrict__ Cf,
    ushort_t* __restrict__ Ch, ushort_t* __restrict__ Cl, float alpha)
{
    extern __shared__ char smg[];
    const uint32_t sb = smem_u32(smg);
    const int tid = threadIdx.x, wid = tid >> 5, lane = tid & 31;
    const int n0 = blockIdx.x * 128, m0 = blockIdx.y * 128;
    float* bias_s = (float*)(smg + G_BIAS);
    if (tid < 128) bias_s[tid] = bias[m0 + tid];

    const int wm = wid & 3, wn = wid >> 2;
    float acc[2][8][4];
#pragma unroll
    for (int ms = 0; ms < 2; ms++)
#pragma unroll
        for (int nt = 0; nt < 8; nt++)
#pragma unroll
            for (int i = 0; i < 4; i++) acc[ms][nt][i] = 0.f;

    const int arow = lane & 15, ak8 = (lane >> 4) * 8;
    const int bj = lane >> 3, br = lane & 7;
    const int bk = (bj & 1) * 8 + br, bn8 = (bj >> 1) * 8;

#define G_CP(kt, buf) do {                                                     \
    const uint32_t base = sb + (buf) * G_BUF;                                  \
    _Pragma("unroll")                                                          \
    for (int i = 0; i < 2; i++) {                                              \
        const int id = i * 256 + tid;                                          \
        const int r = id >> 2, c = id & 3;                                     \
        const size_t so = (size_t)(m0 + r) * KDIM + (kt) * 32 + c * 8;         \
        const uint32_t doff = (uint32_t)(r * 112 + c * 16);                    \
        CP_ASYNC16(base + G_AH + doff, Ah + so);                               \
        CP_ASYNC16(base + G_AL + doff, Al + so);                               \
    }                                                                          \
    _Pragma("unroll")                                                          \
    for (int i = 0; i < 2; i++) {                                              \
        const int id = i * 256 + tid;                                          \
        const int r = id >> 4, c = id & 15;                                    \
        const size_t so = (size_t)((kt) * 32 + r) * SEQ + n0 + c * 8;          \
        const uint32_t doff = (uint32_t)(r * 272 + c * 16);                    \
        CP_ASYNC16(base + G_BH + doff, Bh + so);                               \
        CP_ASYNC16(base + G_BL + doff, Bl + so);                               \
    }                                                                          \
} while (0)

    G_CP(0, 0);
    CP_COMMIT();

    const int NKT = KDIM / 32;
    for (int kt = 0; kt < NKT; kt++) {
        __syncthreads();
        if (kt + 1 < NKT) { G_CP(kt + 1, (kt + 1) & 1); CP_COMMIT(); CP_WAIT(1); }
        else CP_WAIT(0);
        __syncthreads();

        const uint32_t base = sb + (kt & 1) * G_BUF;
#pragma unroll
        for (int ks = 0; ks < 2; ks++) {
            uint32_t aF[2][4], aL[2][4];
#pragma unroll
            for (int ms = 0; ms < 2; ms++) {
                const uint32_t ao = (uint32_t)((wm * 32 + ms * 16 + arow) * LAH + ks * 16 + ak8) * 2;
                LDSM_X4(aF[ms][0], aF[ms][1], aF[ms][2], aF[ms][3], base + G_AH + ao);
                LDSM_X4(aL[ms][0], aL[ms][1], aL[ms][2], aL[ms][3], base + G_AL + ao);
            }
#pragma unroll
            for (int nt16 = 0; nt16 < 4; nt16++) {
                uint32_t bH[4], bL[4];
                const uint32_t bo = (uint32_t)((ks * 16 + bk) * LBH + wn * 64 + nt16 * 16 + bn8) * 2;
                LDSM_X4T(bH[0], bH[1], bH[2], bH[3], base + G_BH + bo);
                LDSM_X4T(bL[0], bL[1], bL[2], bL[3], base + G_BL + bo);
#pragma unroll
                for (int ms = 0; ms < 2; ms++)
#pragma unroll
                    for (int s = 0; s < 2; s++) {
                        float* a4 = acc[ms][nt16 * 2 + s];
                        mma16816(a4, aF[ms], &bH[s * 2]);
                        mma16816(a4, aF[ms], &bL[s * 2]);
                        mma16816(a4, aL[ms], &bH[s * 2]);
                    }
            }
        }
    }

    __syncthreads();
    float* Cs = (float*)smg;
    {
        const int rr = lane >> 2, cc = (lane & 3) * 2;
#pragma unroll
        for (int ms = 0; ms < 2; ms++)
#pragma unroll
            for (int nt = 0; nt < 8; nt++) {
                const int r = wm * 32 + ms * 16 + rr;
                const int c = wn * 64 + nt * 8 + cc;
                Cs[r * 132 + c]           = acc[ms][nt][0];
                Cs[r * 132 + c + 1]       = acc[ms][nt][1];
                Cs[(r + 8) * 132 + c]     = acc[ms][nt][2];
                Cs[(r + 8) * 132 + c + 1] = acc[ms][nt][3];
            }
    }
    __syncthreads();
#pragma unroll
    for (int i = 0; i < 16; i++) {
        const int e = i * 256 + tid;
        const int r = e >> 5, c4 = (e & 31) * 4;
        float4 v = *(const float4*)&Cs[r * 132 + c4];
        const float bi = bias_s[r];
        v.x = alpha * (v.x + bi); v.y = alpha * (v.y + bi);
        v.z = alpha * (v.z + bi); v.w = alpha * (v.w + bi);
        const size_t go = (size_t)(m0 + r) * SEQ + n0 + c4;
        if (Cf) {
            *(float4*)&Cf[go] = v;
        } else {
            uint32_t h0, h1, l0, l1;
            split4(v, h0, h1, l0, l1);
            *(uint2*)&Ch[go] = make_uint2(h0, h1);
            *(uint2*)&Cl[go] = make_uint2(l0, l1);
        }
    }
}

__global__ void __launch_bounds__(256, 2) gemm_qkv(
    const ushort_t* __restrict__ wh, const ushort_t* __restrict__ wl,
    const ushort_t* __restrict__ xh, const ushort_t* __restrict__ xl,
    const float* __restrict__ bq, const float* __restrict__ bk,
    const float* __restrict__ bv,
    ushort_t* __restrict__ ph, ushort_t* __restrict__ pl)
{
    const int gi = blockIdx.z >> 1, bb = blockIdx.z & 1;
    const size_t woff = (size_t)gi * WSZ;
    const size_t xoff = (size_t)gi * XSZ + (size_t)bb * ESZ;
    const float* bias = gi == 0 ? bq : (gi == 1 ? bk : bv);
    const float alpha = gi == 0 ? 0.125f * LOG2E : 1.0f;
    gemm_body(wh + woff, wl + woff, xh + xoff, xl + xoff, bias,
              nullptr, ph + xoff, pl + xoff, alpha);
}
__global__ void __launch_bounds__(256, 2) gemm_wo(
    const ushort_t* __restrict__ wh, const ushort_t* __restrict__ wl,
    const ushort_t* __restrict__ ah, const ushort_t* __restrict__ al,
    const float* __restrict__ bo, float* __restrict__ out)
{
    const size_t off = (size_t)blockIdx.z * ESZ;
    gemm_body(wh, wl, ah + off, al + off, bo, out + off, nullptr, nullptr, 1.0f);
}

// ---------------- tensorized flash attention, K-tile 128 ---------------------
// CTA: (b, h, 128-q tile), 8 warps, warp owns q rows [16w,16w+16).
// KV double buffer: Kh/Kl/Vh/Vl each 64x136h; mask single 64KB buffer,
// read to regs then overwritten by next tile's cp.async.
#define PKH 136
#define KVA 17408            // one array (64*136*2)
#define KVB2 69632           // one buffer (4 arrays)
#define MASK_OFF 139264      // 128 x 132 f32
#define AT_SMEM 206848

__global__ void __launch_bounds__(256) attn_mma(
    const ushort_t* __restrict__ Qh, const ushort_t* __restrict__ Ql,
    const ushort_t* __restrict__ Kh, const ushort_t* __restrict__ Kl,
    const ushort_t* __restrict__ Vh, const ushort_t* __restrict__ Vl,
    const float* __restrict__ MASK,
    ushort_t* __restrict__ Oh, ushort_t* __restrict__ Ol)
{
    extern __shared__ char sma[];
    const uint32_t sb = smem_u32(sma);
    const int tid = threadIdx.x, wid = tid >> 5, lane = tid & 31;
    const int b = blockIdx.z, h = blockIdx.y, q0 = blockIdx.x * 128;

    const size_t hoff = ((size_t)b * EMB + h * DH) * SEQ;
    const float* Mg = MASK + (size_t)b * SEQ * SEQ;

#define A_CPKV(k0, buf) do {                                                   \
    const uint32_t base = sb + (buf) * KVB2;                                   \
    _Pragma("unroll")                                                          \
    for (int i = 0; i < 4; i++) {                                              \
        const int id = i * 256 + tid;                                          \
        const int r = id >> 4, c = id & 15;                                    \
        const size_t so = hoff + (size_t)r * SEQ + (k0) + c * 8;               \
        const uint32_t doff = (uint32_t)(r * 272 + c * 16);                    \
        CP_ASYNC16(base +           doff, Kh + so);                            \
        CP_ASYNC16(base + KVA     + doff, Kl + so);                            \
        CP_ASYNC16(base + 2 * KVA + doff, Vh + so);                            \
        CP_ASYNC16(base + 3 * KVA + doff, Vl + so);                            \
    }                                                                          \
} while (0)

#define A_CPMASK(k0) do {                                                      \
    const uint32_t mb = sb + MASK_OFF;                                         \
    _Pragma("unroll")                                                          \
    for (int i = 0; i < 16; i++) {                                             \
        const int id = i * 256 + tid;                                          \
        const int r = id >> 5, c32 = id & 31;                                  \
        CP_ASYNC16(mb + (uint32_t)(r * 132 + c32 * 4) * 4,                     \
                   Mg + (size_t)((k0) + r) * SEQ + q0 + c32 * 4);              \
    }                                                                          \
} while (0)

    // ---- preamble: Q (into KV buf1) + mask0 (group A); KV0 (group B) ----
    {
        const uint32_t qb = sb + KVB2;
#pragma unroll
        for (int i = 0; i < 4; i++) {
            const int id = i * 256 + tid;
            const int r = id >> 4, c = id & 15;
            const size_t so = hoff + (size_t)r * SEQ + q0 + c * 8;
            const uint32_t doff = (uint32_t)(r * 272 + c * 16);
            CP_ASYNC16(qb + doff, Qh + so);
            CP_ASYNC16(qb + KVA + doff, Ql + so);
        }
    }
    A_CPMASK(0);
    CP_COMMIT();
    A_CPKV(0, 0);
    CP_COMMIT();
    CP_WAIT(1);
    __syncthreads();

    const int arow_k = (lane & 7) + ((lane >> 4) << 3);
    const int amcol  = ((lane >> 3) & 1) * 8;
    uint32_t qfh[4][4], qfl[4][4];
#pragma unroll
    for (int ks = 0; ks < 4; ks++) {
        const uint32_t ao = (uint32_t)((ks * 16 + arow_k) * PKH + wid * 16 + amcol) * 2;
        LDSM_X4T(qfh[ks][0], qfh[ks][1], qfh[ks][2], qfh[ks][3], sb + KVB2 + ao);
        LDSM_X4T(qfl[ks][0], qfl[ks][1], qfl[ks][2], qfl[ks][3], sb + KVB2 + KVA + ao);
    }
    __syncthreads();   // Q region free for KV buf1 (cp issued in iter 0)

    const int bj = lane >> 3, br = lane & 7;
    const int bk = (bj & 1) * 8 + br, bn8 = (bj >> 1) * 8;      // trans (K)
    const int bvrow = ((lane >> 4) & 1) * 8 + br;               // plain (V)
    const int bvk8  = ((lane >> 3) & 1) * 8;

    float o[8][4];
#pragma unroll
    for (int d = 0; d < 8; d++)
#pragma unroll
        for (int j = 0; j < 4; j++) o[d][j] = 0.f;
    float lsum0 = 0.f, lsum1 = 0.f;

    const int qr = wid * 16 + (lane >> 2);
    const int krow2 = 2 * (lane & 3);
    const float* Ms = (const float*)(sma + MASK_OFF);

    const int NT = SEQ / 128;
    for (int kt = 0; kt < NT; kt++) {
        CP_WAIT(0);
        __syncthreads();   // KV kt + mask kt resident; prior reads done

        // ---- mask kt -> regs (accumulator init), then free the buffer ----
        float s[16][4];
#pragma unroll
        for (int nt = 0; nt < 16; nt++) {
            const float* mp = Ms + (nt * 8 + krow2) * 132 + qr;
            s[nt][0] = mp[0]   * LOG2E;
            s[nt][1] = mp[132] * LOG2E;
            s[nt][2] = mp[8]   * LOG2E;
            s[nt][3] = mp[140] * LOG2E;
        }
        __syncthreads();   // all warps consumed the mask buffer

        if (kt + 1 < NT) {
            A_CPKV((kt + 1) * 128, (kt + 1) & 1);
            A_CPMASK((kt + 1) * 128);
            CP_COMMIT();
        }

        const uint32_t kvb = sb + (kt & 1) * KVB2;

        // ---- QK mma (3-pass), 128 keys ----
#pragma unroll
        for (int ks = 0; ks < 4; ks++)
#pragma unroll
            for (int np = 0; np < 8; np++) {
                uint32_t kh[4], kl[4];
                const uint32_t bo = (uint32_t)((ks * 16 + bk) * PKH + np * 16 + bn8) * 2;
                LDSM_X4T(kh[0], kh[1], kh[2], kh[3], kvb + bo);
                LDSM_X4T(kl[0], kl[1], kl[2], kl[3], kvb + KVA + bo);
#pragma unroll
                for (int s2 = 0; s2 < 2; s2++) {
                    float* a4 = s[np * 2 + s2];
                    mma16816(a4, qfh[ks], &kh[s2 * 2]);
                    mma16816(a4, qfh[ks], &kl[s2 * 2]);
                    mma16816(a4, qfl[ks], &kh[s2 * 2]);
                }
            }
        // ---- exp2 + row sums ----
        float rs0 = 0.f, rs1 = 0.f;
#pragma unroll
        for (int nt = 0; nt < 16; nt++) {
#pragma unroll
            for (int j = 0; j < 4; j++) EX2F(s[nt][j], s[nt][j]);
            rs0 += s[nt][0] + s[nt][1];
            rs1 += s[nt][2] + s[nt][3];
        }
        rs0 += __shfl_xor_sync(0xffffffffu, rs0, 1);
        rs0 += __shfl_xor_sync(0xffffffffu, rs0, 2);
        rs1 += __shfl_xor_sync(0xffffffffu, rs1, 1);
        rs1 += __shfl_xor_sync(0xffffffffu, rs1, 2);
        lsum0 += rs0;
        lsum1 += rs1;

        // ---- PV in two 64-key halves: pack P then mma ----
#pragma unroll
        for (int h2 = 0; h2 < 2; h2++) {
            uint32_t pah[4][4], pal[4][4];
#pragma unroll
            for (int ks = 0; ks < 4; ks++) {
                const int kk = h2 * 4 + ks;
                const float* u = s[kk * 2];
                const float* w = s[kk * 2 + 1];
                CVT_BF16X2(pah[ks][0], u[0], u[1]);
                CVT_BF16X2(pah[ks][1], u[2], u[3]);
                CVT_BF16X2(pah[ks][2], w[0], w[1]);
                CVT_BF16X2(pah[ks][3], w[2], w[3]);
                float t0 = u[0] - __uint_as_float(pah[ks][0] << 16);
                float t1 = u[1] - __uint_as_float(pah[ks][0] & 0xffff0000u);
                float t2 = u[2] - __uint_as_float(pah[ks][1] << 16);
                float t3 = u[3] - __uint_as_float(pah[ks][1] & 0xffff0000u);
                CVT_BF16X2(pal[ks][0], t0, t1);
                CVT_BF16X2(pal[ks][1], t2, t3);
                t0 = w[0] - __uint_as_float(pah[ks][2] << 16);
                t1 = w[1] - __uint_as_float(pah[ks][2] & 0xffff0000u);
                t2 = w[2] - __uint_as_float(pah[ks][3] << 16);
                t3 = w[3] - __uint_as_float(pah[ks][3] & 0xffff0000u);
                CVT_BF16X2(pal[ks][2], t0, t1);
                CVT_BF16X2(pal[ks][3], t2, t3);
            }
#pragma unroll
            for (int ks = 0; ks < 4; ks++)
#pragma unroll
                for (int dp = 0; dp < 4; dp++) {
                    uint32_t vh[4], vl[4];
                    const uint32_t bo = (uint32_t)((dp * 16 + bvrow) * PKH
                                                   + (h2 * 4 + ks) * 16 + bvk8) * 2;
                    LDSM_X4(vh[0], vh[1], vh[2], vh[3], kvb + 2 * KVA + bo);
                    LDSM_X4(vl[0], vl[1], vl[2], vl[3], kvb + 3 * KVA + bo);
#pragma unroll
                    for (int s2 = 0; s2 < 2; s2++) {
                        float* a4 = o[dp * 2 + s2];
                        mma16816(a4, pah[ks], &vh[s2 * 2]);
                        mma16816(a4, pah[ks], &vl[s2 * 2]);
                        mma16816(a4, pal[ks], &vh[s2 * 2]);
                    }
                }
        }
    }

    // ---- normalize, transpose via smem, hi/lo coalesced store ----
    const float inv0 = 1.f / lsum0, inv1 = 1.f / lsum1;
    __syncthreads();
    float* Os = (float*)sma;   // [64 dh][132]
#pragma unroll
    for (int d = 0; d < 8; d++) {
        const int dc = d * 8 + krow2;
        Os[dc * 132 + qr]           = o[d][0] * inv0;
        Os[(dc + 1) * 132 + qr]     = o[d][1] * inv0;
        Os[dc * 132 + qr + 8]       = o[d][2] * inv1;
        Os[(dc + 1) * 132 + qr + 8] = o[d][3] * inv1;
    }
    __syncthreads();
#pragma unroll
    for (int i = 0; i < 8; i++) {
        const int e = i * 256 + tid;
        const int r = e >> 5, c4 = (e & 31) * 4;
        const float4 v = *(const float4*)&Os[r * 132 + c4];
        uint32_t h0, h1, l0, l1;
        split4(v, h0, h1, l0, l1);
        const size_t go = hoff + (size_t)r * SEQ + q0 + c4;
        *(uint2*)&Oh[go] = make_uint2(h0, h1);
        *(uint2*)&Ol[go] = make_uint2(l0, l1);
    }
}

// ---------------------------------------------------------------------------
extern "C" void kernel_launch(void* const* d_in, const int* in_sizes, int n_in,
                              void* d_out, int out_size)
{
    const float* q   = (const float*)d_in[0];
    const float* k   = (const float*)d_in[1];
    const float* v   = (const float*)d_in[2];
    const float* msk = (const float*)d_in[3];
    const float* Wq  = (const float*)d_in[4];
    const float* bq  = (const float*)d_in[5];
    const float* Wk  = (const float*)d_in[6];
    const float* bk  = (const float*)d_in[7];
    const float* Wv  = (const float*)d_in[8];
    const float* bv  = (const float*)d_in[9];
    const float* Wo  = (const float*)d_in[10];
    const float* bo  = (const float*)d_in[11];
    float* out = (float*)d_out;

    void *pwh, *pwl, *pxh, *pxl, *pph, *ppl, *path, *patl;
    cudaGetSymbolAddress(&pwh, g_wh);
    cudaGetSymbolAddress(&pwl, g_wl);
    cudaGetSymbolAddress(&pxh, g_xh);
    cudaGetSymbolAddress(&pxl, g_xl);
    cudaGetSymbolAddress(&pph, g_ph);
    cudaGetSymbolAddress(&ppl, g_pl);
    cudaGetSymbolAddress(&path, g_ath);
    cudaGetSymbolAddress(&patl, g_atl);

    ushort_t* wh = (ushort_t*)pwh;  ushort_t* wl = (ushort_t*)pwl;
    ushort_t* xh = (ushort_t*)pxh;  ushort_t* xl = (ushort_t*)pxl;
    ushort_t* ph = (ushort_t*)pph;  ushort_t* pl = (ushort_t*)ppl;
    ushort_t* ath = (ushort_t*)path; ushort_t* atl = (ushort_t*)patl;

    cudaFuncSetAttribute(gemm_qkv, cudaFuncAttributeMaxDynamicSharedMemorySize, GB_SMEM);
    cudaFuncSetAttribute(gemm_wo,  cudaFuncAttributeMaxDynamicSharedMemorySize, GB_SMEM);
    cudaFuncSetAttribute(attn_mma, cudaFuncAttributeMaxDynamicSharedMemorySize, AT_SMEM);

    // 1. converts (2 launches)
    to_hilo_w<<<dim3((unsigned)(WSZ / 1024), 4), 256>>>(Wq, Wk, Wv, Wo, wh, wl);
    to_hilo_x<<<dim3((unsigned)(XSZ / 1024), 3), 256>>>(q, k, v, xh, xl);

    // 2. merged QKV projections (LOG2E*scale folded into Q alpha)
    dim3 gq(SEQ / 128, EMB / 128, 6);
    gemm_qkv<<<gq, 256, GB_SMEM>>>(wh, wl, xh, xl, bq, bk, bv, ph, pl);

    // 3. attention
    dim3 ga(SEQ / 128, NH, BATCH);
    attn_mma<<<ga, 256, AT_SMEM>>>(ph + 0 * XSZ, pl + 0 * XSZ,
                                   ph + 1 * XSZ, pl + 1 * XSZ,
                                   ph + 2 * XSZ, pl + 2 * XSZ,
                                   msk, ath, atl);

    // 4. output projection
    dim3 go(SEQ / 128, EMB / 128, BATCH);
    gemm_wo<<<go, 256, GB_SMEM>>>(wh + 3 * WSZ, wl + 3 * WSZ, ath, atl, bo, out);
}

// round 11
// speedup vs baseline: 2.4013x; 1.1568x over previous
#include <cuda_runtime.h>
#include <cstdint>

#define BATCH 2
#define EMB   1024
#define SEQ   2048
#define NH    16
#define DH    64
#define KDIM  1024
#define LOG2E 1.4426950408889634f
typedef unsigned short ushort_t;

#define WSZ ((size_t)KDIM * EMB)
#define XSZ ((size_t)BATCH * EMB * SEQ)
#define ESZ ((size_t)EMB * SEQ)

// ---------------- scratch ----------------------------------------------------
__device__ ushort_t g_wh[4 * WSZ];
__device__ ushort_t g_wl[4 * WSZ];
__device__ ushort_t g_xh[3 * XSZ];
__device__ ushort_t g_xl[3 * XSZ];
__device__ ushort_t g_ph[3 * XSZ];   // Q hi, K hi, V fp16 (single)
__device__ ushort_t g_pl[3 * XSZ];   // Q lo, K lo, (unused)
__device__ ushort_t g_ath[XSZ];
__device__ ushort_t g_atl[XSZ];

// ---------------- helpers ----------------------------------------------------
__device__ __forceinline__ uint32_t smem_u32(const void* p) {
    uint32_t a;
    asm("{ .reg .u64 t; cvta.to.shared.u64 t, %1; cvt.u32.u64 %0, t; }" : "=r"(a) : "l"(p));
    return a;
}
__device__ __forceinline__ void mma16816(float* c, const uint32_t* a, const uint32_t* b) {
    asm volatile("mma.sync.aligned.m16n8k16.row.col.f32.bf16.bf16.f32 "
        "{%0,%1,%2,%3}, {%4,%5,%6,%7}, {%8,%9}, {%0,%1,%2,%3};"
        : "+f"(c[0]), "+f"(c[1]), "+f"(c[2]), "+f"(c[3])
        : "r"(a[0]), "r"(a[1]), "r"(a[2]), "r"(a[3]), "r"(b[0]), "r"(b[1]));
}
__device__ __forceinline__ void mma16816f(float* c, const uint32_t* a, const uint32_t* b) {
    asm volatile("mma.sync.aligned.m16n8k16.row.col.f32.f16.f16.f32 "
        "{%0,%1,%2,%3}, {%4,%5,%6,%7}, {%8,%9}, {%0,%1,%2,%3};"
        : "+f"(c[0]), "+f"(c[1]), "+f"(c[2]), "+f"(c[3])
        : "r"(a[0]), "r"(a[1]), "r"(a[2]), "r"(a[3]), "r"(b[0]), "r"(b[1]));
}
#define LDSM_X4(r0,r1,r2,r3,addr) \
    asm volatile("ldmatrix.sync.aligned.m8n8.x4.shared.b16 {%0,%1,%2,%3}, [%4];" \
                 : "=r"(r0),"=r"(r1),"=r"(r2),"=r"(r3) : "r"(addr))
#define LDSM_X4T(r0,r1,r2,r3,addr) \
    asm volatile("ldmatrix.sync.aligned.m8n8.x4.trans.shared.b16 {%0,%1,%2,%3}, [%4];" \
                 : "=r"(r0),"=r"(r1),"=r"(r2),"=r"(r3) : "r"(addr))
#define CVT_BF16X2(res,a,b) asm("cvt.rn.bf16x2.f32 %0, %1, %2;" : "=r"(res) : "f"(b), "f"(a))
#define CVT_F16X2(res,a,b)  asm("cvt.rn.f16x2.f32 %0, %1, %2;" : "=r"(res) : "f"(b), "f"(a))
#define EX2F(y,x) asm("ex2.approx.f32 %0, %1;" : "=f"(y) : "f"(x))
#define CP_ASYNC16(dst, src) \
    asm volatile("cp.async.cg.shared.global [%0], [%1], 16;" :: "r"(dst), "l"(src) : "memory")
#define CP_COMMIT() asm volatile("cp.async.commit_group;" ::: "memory")
#define CP_WAIT(n) asm volatile("cp.async.wait_group %0;" :: "n"(n) : "memory")

__device__ __forceinline__ void split4(const float4 v, uint32_t& h0, uint32_t& h1,
                                       uint32_t& l0, uint32_t& l1) {
    CVT_BF16X2(h0, v.x, v.y);
    CVT_BF16X2(h1, v.z, v.w);
    const float r0 = v.x - __uint_as_float(h0 << 16);
    const float r1 = v.y - __uint_as_float(h0 & 0xffff0000u);
    const float r2 = v.z - __uint_as_float(h1 << 16);
    const float r3 = v.w - __uint_as_float(h1 & 0xffff0000u);
    CVT_BF16X2(l0, r0, r1);
    CVT_BF16X2(l1, r2, r3);
}

// ---------------- merged converts --------------------------------------------
__global__ void __launch_bounds__(256) to_hilo_w(
    const float* __restrict__ w0, const float* __restrict__ w1,
    const float* __restrict__ w2, const float* __restrict__ w3,
    ushort_t* __restrict__ hi, ushort_t* __restrict__ lo)
{
    const int g = blockIdx.y;
    const float* src = g == 0 ? w0 : (g == 1 ? w1 : (g == 2 ? w2 : w3));
    const size_t i = ((size_t)blockIdx.x * 256 + threadIdx.x) * 4;
    const float4 v = *(const float4*)&src[i];
    uint32_t h0, h1, l0, l1;
    split4(v, h0, h1, l0, l1);
    *(uint2*)&hi[g * WSZ + i] = make_uint2(h0, h1);
    *(uint2*)&lo[g * WSZ + i] = make_uint2(l0, l1);
}
__global__ void __launch_bounds__(256) to_hilo_x(
    const float* __restrict__ x0, const float* __restrict__ x1,
    const float* __restrict__ x2,
    ushort_t* __restrict__ hi, ushort_t* __restrict__ lo)
{
    const int g = blockIdx.y;
    const float* src = g == 0 ? x0 : (g == 1 ? x1 : x2);
    const size_t i = ((size_t)blockIdx.x * 256 + threadIdx.x) * 4;
    const float4 v = *(const float4*)&src[i];
    uint32_t h0, h1, l0, l1;
    split4(v, h0, h1, l0, l1);
    *(uint2*)&hi[g * XSZ + i] = make_uint2(h0, h1);
    *(uint2*)&lo[g * XSZ + i] = make_uint2(l0, l1);
}

// ---------------- GEMM body (pure bf16 cp.async path) -------------------------
// mode: 0 = f32 out, 1 = bf16 hi/lo out, 2 = fp16 single out
#define LAH 56
#define LBH 136
#define G_AH 0
#define G_AL 14336
#define G_BH 28672
#define G_BL 37376
#define G_BUF 46080
#define G_BIAS 92160
#define GB_SMEM 92672

__device__ __forceinline__ void gemm_body(
    const ushort_t* __restrict__ Ah, const ushort_t* __restrict__ Al,
    const ushort_t* __restrict__ Bh, const ushort_t* __restrict__ Bl,
    const float* __restrict__ bias, float* __restrict__ Cf,
    ushort_t* __restrict__ Ch, ushort_t* __restrict__ Cl,
    float alpha, int mode)
{
    extern __shared__ char smg[];
    const uint32_t sb = smem_u32(smg);
    const int tid = threadIdx.x, wid = tid >> 5, lane = tid & 31;
    const int n0 = blockIdx.x * 128, m0 = blockIdx.y * 128;
    float* bias_s = (float*)(smg + G_BIAS);
    if (tid < 128) bias_s[tid] = bias[m0 + tid];

    const int wm = wid & 3, wn = wid >> 2;
    float acc[2][8][4];
#pragma unroll
    for (int ms = 0; ms < 2; ms++)
#pragma unroll
        for (int nt = 0; nt < 8; nt++)
#pragma unroll
            for (int i = 0; i < 4; i++) acc[ms][nt][i] = 0.f;

    const int arow = lane & 15, ak8 = (lane >> 4) * 8;
    const int bj = lane >> 3, br = lane & 7;
    const int bk = (bj & 1) * 8 + br, bn8 = (bj >> 1) * 8;

#define G_CP(kt, buf) do {                                                     \
    const uint32_t base = sb + (buf) * G_BUF;                                  \
    _Pragma("unroll")                                                          \
    for (int i = 0; i < 2; i++) {                                              \
        const int id = i * 256 + tid;                                          \
        const int r = id >> 2, c = id & 3;                                     \
        const size_t so = (size_t)(m0 + r) * KDIM + (kt) * 32 + c * 8;         \
        const uint32_t doff = (uint32_t)(r * 112 + c * 16);                    \
        CP_ASYNC16(base + G_AH + doff, Ah + so);                               \
        CP_ASYNC16(base + G_AL + doff, Al + so);                               \
    }                                                                          \
    _Pragma("unroll")                                                          \
    for (int i = 0; i < 2; i++) {                                              \
        const int id = i * 256 + tid;                                          \
        const int r = id >> 4, c = id & 15;                                    \
        const size_t so = (size_t)((kt) * 32 + r) * SEQ + n0 + c * 8;          \
        const uint32_t doff = (uint32_t)(r * 272 + c * 16);                    \
        CP_ASYNC16(base + G_BH + doff, Bh + so);                               \
        CP_ASYNC16(base + G_BL + doff, Bl + so);                               \
    }                                                                          \
} while (0)

    G_CP(0, 0);
    CP_COMMIT();

    const int NKT = KDIM / 32;
    for (int kt = 0; kt < NKT; kt++) {
        __syncthreads();
        if (kt + 1 < NKT) { G_CP(kt + 1, (kt + 1) & 1); CP_COMMIT(); CP_WAIT(1); }
        else CP_WAIT(0);
        __syncthreads();

        const uint32_t base = sb + (kt & 1) * G_BUF;
#pragma unroll
        for (int ks = 0; ks < 2; ks++) {
            uint32_t aF[2][4], aL[2][4];
#pragma unroll
            for (int ms = 0; ms < 2; ms++) {
                const uint32_t ao = (uint32_t)((wm * 32 + ms * 16 + arow) * LAH + ks * 16 + ak8) * 2;
                LDSM_X4(aF[ms][0], aF[ms][1], aF[ms][2], aF[ms][3], base + G_AH + ao);
                LDSM_X4(aL[ms][0], aL[ms][1], aL[ms][2], aL[ms][3], base + G_AL + ao);
            }
#pragma unroll
            for (int nt16 = 0; nt16 < 4; nt16++) {
                uint32_t bH[4], bL[4];
                const uint32_t bo = (uint32_t)((ks * 16 + bk) * LBH + wn * 64 + nt16 * 16 + bn8) * 2;
                LDSM_X4T(bH[0], bH[1], bH[2], bH[3], base + G_BH + bo);
                LDSM_X4T(bL[0], bL[1], bL[2], bL[3], base + G_BL + bo);
#pragma unroll
                for (int ms = 0; ms < 2; ms++)
#pragma unroll
                    for (int s = 0; s < 2; s++) {
                        float* a4 = acc[ms][nt16 * 2 + s];
                        mma16816(a4, aF[ms], &bH[s * 2]);
                        mma16816(a4, aF[ms], &bL[s * 2]);
                        mma16816(a4, aL[ms], &bH[s * 2]);
                    }
            }
        }
    }

    __syncthreads();
    float* Cs = (float*)smg;
    {
        const int rr = lane >> 2, cc = (lane & 3) * 2;
#pragma unroll
        for (int ms = 0; ms < 2; ms++)
#pragma unroll
            for (int nt = 0; nt < 8; nt++) {
                const int r = wm * 32 + ms * 16 + rr;
                const int c = wn * 64 + nt * 8 + cc;
                Cs[r * 132 + c]           = acc[ms][nt][0];
                Cs[r * 132 + c + 1]       = acc[ms][nt][1];
                Cs[(r + 8) * 132 + c]     = acc[ms][nt][2];
                Cs[(r + 8) * 132 + c + 1] = acc[ms][nt][3];
            }
    }
    __syncthreads();
#pragma unroll
    for (int i = 0; i < 16; i++) {
        const int e = i * 256 + tid;
        const int r = e >> 5, c4 = (e & 31) * 4;
        float4 v = *(const float4*)&Cs[r * 132 + c4];
        const float bi = bias_s[r];
        v.x = alpha * (v.x + bi); v.y = alpha * (v.y + bi);
        v.z = alpha * (v.z + bi); v.w = alpha * (v.w + bi);
        const size_t go = (size_t)(m0 + r) * SEQ + n0 + c4;
        if (mode == 0) {
            *(float4*)&Cf[go] = v;
        } else if (mode == 1) {
            uint32_t h0, h1, l0, l1;
            split4(v, h0, h1, l0, l1);
            *(uint2*)&Ch[go] = make_uint2(h0, h1);
            *(uint2*)&Cl[go] = make_uint2(l0, l1);
        } else {
            uint32_t f0, f1;
            CVT_F16X2(f0, v.x, v.y);
            CVT_F16X2(f1, v.z, v.w);
            *(uint2*)&Ch[go] = make_uint2(f0, f1);
        }
    }
}

__global__ void __launch_bounds__(256, 2) gemm_qkv(
    const ushort_t* __restrict__ wh, const ushort_t* __restrict__ wl,
    const ushort_t* __restrict__ xh, const ushort_t* __restrict__ xl,
    const float* __restrict__ bq, const float* __restrict__ bk,
    const float* __restrict__ bv,
    ushort_t* __restrict__ ph, ushort_t* __restrict__ pl)
{
    const int gi = blockIdx.z >> 1, bb = blockIdx.z & 1;
    const size_t woff = (size_t)gi * WSZ;
    const size_t xoff = (size_t)gi * XSZ + (size_t)bb * ESZ;
    const float* bias = gi == 0 ? bq : (gi == 1 ? bk : bv);
    const float alpha = gi == 0 ? 0.125f * LOG2E : 1.0f;
    const int mode = gi == 2 ? 2 : 1;   // V -> fp16 single
    gemm_body(wh + woff, wl + woff, xh + xoff, xl + xoff, bias,
              nullptr, ph + xoff, pl + xoff, alpha, mode);
}
__global__ void __launch_bounds__(256, 2) gemm_wo(
    const ushort_t* __restrict__ wh, const ushort_t* __restrict__ wl,
    const ushort_t* __restrict__ ah, const ushort_t* __restrict__ al,
    const float* __restrict__ bo, float* __restrict__ out)
{
    const size_t off = (size_t)blockIdx.z * ESZ;
    gemm_body(wh, wl, ah + off, al + off, bo, out + off, nullptr, nullptr, 1.0f, 0);
}

// ---------------- flash attention: 128-key staging, 64-key halves ------------
// QK 3-pass bf16 (Kh/Kl), PV 1-pass fp16 (Vf). Mask single 128-row buffer
// (67584 B) with mid-tile barrier; KV double-buffered (3 arrays each).
#define PKH 136
#define KVA 17408            // one array (64 x 136 halves)
#define KVB2 52224           // buffer: Kh, Kl, Vf
#define MASK_OFF 104448      // 128 x 132 f32 = 67584 B
#define AT_SMEM 172032       // = MASK_OFF + 67584  (R10 bug: was 138240)

__global__ void __launch_bounds__(256) attn_mma(
    const ushort_t* __restrict__ Qh, const ushort_t* __restrict__ Ql,
    const ushort_t* __restrict__ Kh, const ushort_t* __restrict__ Kl,
    const ushort_t* __restrict__ Vf,
    const float* __restrict__ MASK,
    ushort_t* __restrict__ Oh, ushort_t* __restrict__ Ol)
{
    extern __shared__ char sma[];
    const uint32_t sb = smem_u32(sma);
    const int tid = threadIdx.x, wid = tid >> 5, lane = tid & 31;
    const int b = blockIdx.z, h = blockIdx.y, q0 = blockIdx.x * 128;

    const size_t hoff = ((size_t)b * EMB + h * DH) * SEQ;
    const float* Mg = MASK + (size_t)b * SEQ * SEQ;

#define A_CPKV(k0, buf) do {                                                   \
    const uint32_t base = sb + (buf) * KVB2;                                   \
    _Pragma("unroll")                                                          \
    for (int i = 0; i < 4; i++) {                                              \
        const int id = i * 256 + tid;                                          \
        const int r = id >> 4, c = id & 15;                                    \
        const size_t so = hoff + (size_t)r * SEQ + (k0) + c * 8;               \
        const uint32_t doff = (uint32_t)(r * 272 + c * 16);                    \
        CP_ASYNC16(base +           doff, Kh + so);                            \
        CP_ASYNC16(base + KVA     + doff, Kl + so);                            \
        CP_ASYNC16(base + 2 * KVA + doff, Vf + so);                            \
    }                                                                          \
} while (0)

#define A_CPMASK(k0) do {                                                      \
    const uint32_t mb = sb + MASK_OFF;                                         \
    _Pragma("unroll")                                                          \
    for (int i = 0; i < 16; i++) {                                             \
        const int id = i * 256 + tid;                                          \
        const int r = id >> 5, c32 = id & 31;                                  \
        CP_ASYNC16(mb + (uint32_t)(r * 132 + c32 * 4) * 4,                     \
                   Mg + (size_t)((k0) + r) * SEQ + q0 + c32 * 4);              \
    }                                                                          \
} while (0)

    // ---- preamble: Q (into KV buf1) + mask0 (group A); KV0 (group B) ----
    {
        const uint32_t qb = sb + KVB2;
#pragma unroll
        for (int i = 0; i < 4; i++) {
            const int id = i * 256 + tid;
            const int r = id >> 4, c = id & 15;
            const size_t so = hoff + (size_t)r * SEQ + q0 + c * 8;
            const uint32_t doff = (uint32_t)(r * 272 + c * 16);
            CP_ASYNC16(qb + doff, Qh + so);
            CP_ASYNC16(qb + KVA + doff, Ql + so);
        }
    }
    A_CPMASK(0);
    CP_COMMIT();
    A_CPKV(0, 0);
    CP_COMMIT();
    CP_WAIT(1);
    __syncthreads();

    const int arow_k = (lane & 7) + ((lane >> 4) << 3);
    const int amcol  = ((lane >> 3) & 1) * 8;
    uint32_t qfh[4][4], qfl[4][4];
#pragma unroll
    for (int ks = 0; ks < 4; ks++) {
        const uint32_t ao = (uint32_t)((ks * 16 + arow_k) * PKH + wid * 16 + amcol) * 2;
        LDSM_X4T(qfh[ks][0], qfh[ks][1], qfh[ks][2], qfh[ks][3], sb + KVB2 + ao);
        LDSM_X4T(qfl[ks][0], qfl[ks][1], qfl[ks][2], qfl[ks][3], sb + KVB2 + KVA + ao);
    }
    __syncthreads();   // Q region free for KV buf1 (cp issued in iter 0)

    const int bj = lane >> 3, br = lane & 7;
    const int bk = (bj & 1) * 8 + br, bn8 = (bj >> 1) * 8;      // trans (K)
    const int bvrow = ((lane >> 4) & 1) * 8 + br;               // plain (V)
    const int bvk8  = ((lane >> 3) & 1) * 8;

    float o[8][4];
#pragma unroll
    for (int d = 0; d < 8; d++)
#pragma unroll
        for (int j = 0; j < 4; j++) o[d][j] = 0.f;
    float lsum0 = 0.f, lsum1 = 0.f;

    const int qr = wid * 16 + (lane >> 2);
    const int krow2 = 2 * (lane & 3);
    const float* Ms = (const float*)(sma + MASK_OFF);

    const int NT = SEQ / 128;
    for (int kt = 0; kt < NT; kt++) {
        CP_WAIT(0);
        __syncthreads();   // KV kt + mask kt resident

        const uint32_t kvb = sb + (kt & 1) * KVB2;

#pragma unroll
        for (int h2 = 0; h2 < 2; h2++) {
            // ---- mask (this half) -> accumulator init ----
            float s[8][4];
#pragma unroll
            for (int nt = 0; nt < 8; nt++) {
                const float* mp = Ms + (h2 * 64 + nt * 8 + krow2) * 132 + qr;
                s[nt][0] = mp[0]   * LOG2E;
                s[nt][1] = mp[132] * LOG2E;
                s[nt][2] = mp[8]   * LOG2E;
                s[nt][3] = mp[140] * LOG2E;
            }
            if (h2 == 1) {
                __syncthreads();   // all warps done with mask buffer
                if (kt + 1 < NT) {
                    A_CPKV((kt + 1) * 128, (kt + 1) & 1);
                    A_CPMASK((kt + 1) * 128);
                    CP_COMMIT();
                }
            }
            // ---- QK mma (3-pass bf16), 64 keys ----
#pragma unroll
            for (int ks = 0; ks < 4; ks++)
#pragma unroll
                for (int np = 0; np < 4; np++) {
                    uint32_t kh[4], kl[4];
                    const uint32_t bo = (uint32_t)((ks * 16 + bk) * PKH
                                                   + h2 * 64 + np * 16 + bn8) * 2;
                    LDSM_X4T(kh[0], kh[1], kh[2], kh[3], kvb + bo);
                    LDSM_X4T(kl[0], kl[1], kl[2], kl[3], kvb + KVA + bo);
#pragma unroll
                    for (int s2 = 0; s2 < 2; s2++) {
                        float* a4 = s[np * 2 + s2];
                        mma16816(a4, qfh[ks], &kh[s2 * 2]);
                        mma16816(a4, qfh[ks], &kl[s2 * 2]);
                        mma16816(a4, qfl[ks], &kh[s2 * 2]);
                    }
                }
            // ---- exp2 + row sums ----
            float rs0 = 0.f, rs1 = 0.f;
#pragma unroll
            for (int nt = 0; nt < 8; nt++) {
#pragma unroll
                for (int j = 0; j < 4; j++) EX2F(s[nt][j], s[nt][j]);
                rs0 += s[nt][0] + s[nt][1];
                rs1 += s[nt][2] + s[nt][3];
            }
            rs0 += __shfl_xor_sync(0xffffffffu, rs0, 1);
            rs0 += __shfl_xor_sync(0xffffffffu, rs0, 2);
            rs1 += __shfl_xor_sync(0xffffffffu, rs1, 1);
            rs1 += __shfl_xor_sync(0xffffffffu, rs1, 2);
            lsum0 += rs0;
            lsum1 += rs1;

            // ---- pack P as fp16 (single) ----
            uint32_t pa[4][4];
#pragma unroll
            for (int ks = 0; ks < 4; ks++) {
                const float* u = s[ks * 2];
                const float* w = s[ks * 2 + 1];
                CVT_F16X2(pa[ks][0], u[0], u[1]);
                CVT_F16X2(pa[ks][1], u[2], u[3]);
                CVT_F16X2(pa[ks][2], w[0], w[1]);
                CVT_F16X2(pa[ks][3], w[2], w[3]);
            }
            // ---- PV mma (1-pass fp16): O += P @ V ----
#pragma unroll
            for (int ks = 0; ks < 4; ks++)
#pragma unroll
                for (int dp = 0; dp < 4; dp++) {
                    uint32_t vf[4];
                    const uint32_t bo = (uint32_t)((dp * 16 + bvrow) * PKH
                                                   + h2 * 64 + ks * 16 + bvk8) * 2;
                    LDSM_X4(vf[0], vf[1], vf[2], vf[3], kvb + 2 * KVA + bo);
#pragma unroll
                    for (int s2 = 0; s2 < 2; s2++)
                        mma16816f(o[dp * 2 + s2], pa[ks], &vf[s2 * 2]);
                }
        }
    }

    // ---- normalize, transpose via smem, hi/lo coalesced store ----
    const float inv0 = 1.f / lsum0, inv1 = 1.f / lsum1;
    __syncthreads();
    float* Os = (float*)sma;   // [64 dh][132]
#pragma unroll
    for (int d = 0; d < 8; d++) {
        const int dc = d * 8 + krow2;
        Os[dc * 132 + qr]           = o[d][0] * inv0;
        Os[(dc + 1) * 132 + qr]     = o[d][1] * inv0;
        Os[dc * 132 + qr + 8]       = o[d][2] * inv1;
        Os[(dc + 1) * 132 + qr + 8] = o[d][3] * inv1;
    }
    __syncthreads();
#pragma unroll
    for (int i = 0; i < 8; i++) {
        const int e = i * 256 + tid;
        const int r = e >> 5, c4 = (e & 31) * 4;
        const float4 v = *(const float4*)&Os[r * 132 + c4];
        uint32_t h0, h1, l0, l1;
        split4(v, h0, h1, l0, l1);
        const size_t go = hoff + (size_t)r * SEQ + q0 + c4;
        *(uint2*)&Oh[go] = make_uint2(h0, h1);
        *(uint2*)&Ol[go] = make_uint2(l0, l1);
    }
}

// ---------------------------------------------------------------------------
extern "C" void kernel_launch(void* const* d_in, const int* in_sizes, int n_in,
                              void* d_out, int out_size)
{
    const float* q   = (const float*)d_in[0];
    const float* k   = (const float*)d_in[1];
    const float* v   = (const float*)d_in[2];
    const float* msk = (const float*)d_in[3];
    const float* Wq  = (const float*)d_in[4];
    const float* bq  = (const float*)d_in[5];
    const float* Wk  = (const float*)d_in[6];
    const float* bk  = (const float*)d_in[7];
    const float* Wv  = (const float*)d_in[8];
    const float* bv  = (const float*)d_in[9];
    const float* Wo  = (const float*)d_in[10];
    const float* bo  = (const float*)d_in[11];
    float* out = (float*)d_out;

    void *pwh, *pwl, *pxh, *pxl, *pph, *ppl, *path, *patl;
    cudaGetSymbolAddress(&pwh, g_wh);
    cudaGetSymbolAddress(&pwl, g_wl);
    cudaGetSymbolAddress(&pxh, g_xh);
    cudaGetSymbolAddress(&pxl, g_xl);
    cudaGetSymbolAddress(&pph, g_ph);
    cudaGetSymbolAddress(&ppl, g_pl);
    cudaGetSymbolAddress(&path, g_ath);
    cudaGetSymbolAddress(&patl, g_atl);

    ushort_t* wh = (ushort_t*)pwh;  ushort_t* wl = (ushort_t*)pwl;
    ushort_t* xh = (ushort_t*)pxh;  ushort_t* xl = (ushort_t*)pxl;
    ushort_t* ph = (ushort_t*)pph;  ushort_t* pl = (ushort_t*)ppl;
    ushort_t* ath = (ushort_t*)path; ushort_t* atl = (ushort_t*)patl;

    cudaFuncSetAttribute(gemm_qkv, cudaFuncAttributeMaxDynamicSharedMemorySize, GB_SMEM);
    cudaFuncSetAttribute(gemm_wo,  cudaFuncAttributeMaxDynamicSharedMemorySize, GB_SMEM);
    cudaFuncSetAttribute(attn_mma, cudaFuncAttributeMaxDynamicSharedMemorySize, AT_SMEM);

    // 1. converts
    to_hilo_w<<<dim3((unsigned)(WSZ / 1024), 4), 256>>>(Wq, Wk, Wv, Wo, wh, wl);
    to_hilo_x<<<dim3((unsigned)(XSZ / 1024), 3), 256>>>(q, k, v, xh, xl);

    // 2. merged QKV projections (V emits fp16 single)
    dim3 gq(SEQ / 128, EMB / 128, 6);
    gemm_qkv<<<gq, 256, GB_SMEM>>>(wh, wl, xh, xl, bq, bk, bv, ph, pl);

    // 3. attention
    dim3 ga(SEQ / 128, NH, BATCH);
    attn_mma<<<ga, 256, AT_SMEM>>>(ph + 0 * XSZ, pl + 0 * XSZ,
                                   ph + 1 * XSZ, pl + 1 * XSZ,
                                   ph + 2 * XSZ,
                                   msk, ath, atl);

    // 4. output projection
    dim3 go(SEQ / 128, EMB / 128, BATCH);
    gemm_wo<<<go, 256, GB_SMEM>>>(wh + 3 * WSZ, wl + 3 * WSZ, ath, atl, bo, out);
}

// round 12
// speedup vs baseline: 2.5931x; 1.0799x over previous
#include <cuda_runtime.h>
#include <cuda_fp16.h>
#include <cstdint>

#define BATCH 2
#define EMB   1024
#define SEQ   2048
#define NH    16
#define DH    64
#define KDIM  1024
#define LOG2E 1.4426950408889634f
typedef unsigned short ushort_t;

#define WSZ ((size_t)KDIM * EMB)
#define XSZ ((size_t)BATCH * EMB * SEQ)
#define ESZ ((size_t)EMB * SEQ)

// ---------------- scratch ----------------------------------------------------
__device__ ushort_t g_wh[4 * WSZ];
__device__ ushort_t g_wl[4 * WSZ];
__device__ ushort_t g_xh[3 * XSZ];
__device__ ushort_t g_xl[3 * XSZ];
__device__ ushort_t g_ph[3 * XSZ];   // Q fp16-hi, K fp16, V fp16
__device__ ushort_t g_pl[3 * XSZ];   // Q fp16-lo, (unused), (unused)
__device__ ushort_t g_ath[XSZ];
__device__ ushort_t g_atl[XSZ];

// ---------------- helpers ----------------------------------------------------
__device__ __forceinline__ uint32_t smem_u32(const void* p) {
    uint32_t a;
    asm("{ .reg .u64 t; cvta.to.shared.u64 t, %1; cvt.u32.u64 %0, t; }" : "=r"(a) : "l"(p));
    return a;
}
__device__ __forceinline__ void mma16816(float* c, const uint32_t* a, const uint32_t* b) {
    asm volatile("mma.sync.aligned.m16n8k16.row.col.f32.bf16.bf16.f32 "
        "{%0,%1,%2,%3}, {%4,%5,%6,%7}, {%8,%9}, {%0,%1,%2,%3};"
        : "+f"(c[0]), "+f"(c[1]), "+f"(c[2]), "+f"(c[3])
        : "r"(a[0]), "r"(a[1]), "r"(a[2]), "r"(a[3]), "r"(b[0]), "r"(b[1]));
}
__device__ __forceinline__ void mma16816f(float* c, const uint32_t* a, const uint32_t* b) {
    asm volatile("mma.sync.aligned.m16n8k16.row.col.f32.f16.f16.f32 "
        "{%0,%1,%2,%3}, {%4,%5,%6,%7}, {%8,%9}, {%0,%1,%2,%3};"
        : "+f"(c[0]), "+f"(c[1]), "+f"(c[2]), "+f"(c[3])
        : "r"(a[0]), "r"(a[1]), "r"(a[2]), "r"(a[3]), "r"(b[0]), "r"(b[1]));
}
#define LDSM_X4(r0,r1,r2,r3,addr) \
    asm volatile("ldmatrix.sync.aligned.m8n8.x4.shared.b16 {%0,%1,%2,%3}, [%4];" \
                 : "=r"(r0),"=r"(r1),"=r"(r2),"=r"(r3) : "r"(addr))
#define LDSM_X4T(r0,r1,r2,r3,addr) \
    asm volatile("ldmatrix.sync.aligned.m8n8.x4.trans.shared.b16 {%0,%1,%2,%3}, [%4];" \
                 : "=r"(r0),"=r"(r1),"=r"(r2),"=r"(r3) : "r"(addr))
#define CVT_BF16X2(res,a,b) asm("cvt.rn.bf16x2.f32 %0, %1, %2;" : "=r"(res) : "f"(b), "f"(a))
#define CVT_F16X2(res,a,b)  asm("cvt.rn.f16x2.f32 %0, %1, %2;" : "=r"(res) : "f"(b), "f"(a))
#define EX2F(y,x) asm("ex2.approx.f32 %0, %1;" : "=f"(y) : "f"(x))
#define CP_ASYNC16(dst, src) \
    asm volatile("cp.async.cg.shared.global [%0], [%1], 16;" :: "r"(dst), "l"(src) : "memory")
#define CP_COMMIT() asm volatile("cp.async.commit_group;" ::: "memory")
#define CP_WAIT(n) asm volatile("cp.async.wait_group %0;" :: "n"(n) : "memory")

__device__ __forceinline__ void split4(const float4 v, uint32_t& h0, uint32_t& h1,
                                       uint32_t& l0, uint32_t& l1) {
    CVT_BF16X2(h0, v.x, v.y);
    CVT_BF16X2(h1, v.z, v.w);
    const float r0 = v.x - __uint_as_float(h0 << 16);
    const float r1 = v.y - __uint_as_float(h0 & 0xffff0000u);
    const float r2 = v.z - __uint_as_float(h1 << 16);
    const float r3 = v.w - __uint_as_float(h1 & 0xffff0000u);
    CVT_BF16X2(l0, r0, r1);
    CVT_BF16X2(l1, r2, r3);
}

// fp16 hi/lo split of a float4
__device__ __forceinline__ void split4_f16(const float4 v, uint32_t& h0, uint32_t& h1,
                                           uint32_t& l0, uint32_t& l1) {
    CVT_F16X2(h0, v.x, v.y);
    CVT_F16X2(h1, v.z, v.w);
    const __half2 hx = *(const __half2*)&h0;
    const __half2 hy = *(const __half2*)&h1;
    const float r0 = v.x - __half2float(__low2half(hx));
    const float r1 = v.y - __half2float(__high2half(hx));
    const float r2 = v.z - __half2float(__low2half(hy));
    const float r3 = v.w - __half2float(__high2half(hy));
    CVT_F16X2(l0, r0, r1);
    CVT_F16X2(l1, r2, r3);
}

// ---------------- merged converts --------------------------------------------
__global__ void __launch_bounds__(256) to_hilo_w(
    const float* __restrict__ w0, const float* __restrict__ w1,
    const float* __restrict__ w2, const float* __restrict__ w3,
    ushort_t* __restrict__ hi, ushort_t* __restrict__ lo)
{
    const int g = blockIdx.y;
    const float* src = g == 0 ? w0 : (g == 1 ? w1 : (g == 2 ? w2 : w3));
    const size_t i = ((size_t)blockIdx.x * 256 + threadIdx.x) * 4;
    const float4 v = *(const float4*)&src[i];
    uint32_t h0, h1, l0, l1;
    split4(v, h0, h1, l0, l1);
    *(uint2*)&hi[g * WSZ + i] = make_uint2(h0, h1);
    *(uint2*)&lo[g * WSZ + i] = make_uint2(l0, l1);
}
__global__ void __launch_bounds__(256) to_hilo_x(
    const float* __restrict__ x0, const float* __restrict__ x1,
    const float* __restrict__ x2,
    ushort_t* __restrict__ hi, ushort_t* __restrict__ lo)
{
    const int g = blockIdx.y;
    const float* src = g == 0 ? x0 : (g == 1 ? x1 : x2);
    const size_t i = ((size_t)blockIdx.x * 256 + threadIdx.x) * 4;
    const float4 v = *(const float4*)&src[i];
    uint32_t h0, h1, l0, l1;
    split4(v, h0, h1, l0, l1);
    *(uint2*)&hi[g * XSZ + i] = make_uint2(h0, h1);
    *(uint2*)&lo[g * XSZ + i] = make_uint2(l0, l1);
}

// ---------------- GEMM body (pure bf16 cp.async path) -------------------------
// mode: 0 = f32 out, 1 = bf16 hi/lo out, 2 = fp16 single out, 3 = fp16 hi/lo out
#define LAH 56
#define LBH 136
#define G_AH 0
#define G_AL 14336
#define G_BH 28672
#define G_BL 37376
#define G_BUF 46080
#define G_BIAS 92160
#define GB_SMEM 92672

__device__ __forceinline__ void gemm_body(
    const ushort_t* __restrict__ Ah, const ushort_t* __restrict__ Al,
    const ushort_t* __restrict__ Bh, const ushort_t* __restrict__ Bl,
    const float* __restrict__ bias, float* __restrict__ Cf,
    ushort_t* __restrict__ Ch, ushort_t* __restrict__ Cl,
    float alpha, int mode)
{
    extern __shared__ char smg[];
    const uint32_t sb = smem_u32(smg);
    const int tid = threadIdx.x, wid = tid >> 5, lane = tid & 31;
    const int n0 = blockIdx.x * 128, m0 = blockIdx.y * 128;
    float* bias_s = (float*)(smg + G_BIAS);
    if (tid < 128) bias_s[tid] = bias[m0 + tid];

    const int wm = wid & 3, wn = wid >> 2;
    float acc[2][8][4];
#pragma unroll
    for (int ms = 0; ms < 2; ms++)
#pragma unroll
        for (int nt = 0; nt < 8; nt++)
#pragma unroll
            for (int i = 0; i < 4; i++) acc[ms][nt][i] = 0.f;

    const int arow = lane & 15, ak8 = (lane >> 4) * 8;
    const int bj = lane >> 3, br = lane & 7;
    const int bk = (bj & 1) * 8 + br, bn8 = (bj >> 1) * 8;

#define G_CP(kt, buf) do {                                                     \
    const uint32_t base = sb + (buf) * G_BUF;                                  \
    _Pragma("unroll")                                                          \
    for (int i = 0; i < 2; i++) {                                              \
        const int id = i * 256 + tid;                                          \
        const int r = id >> 2, c = id & 3;                                     \
        const size_t so = (size_t)(m0 + r) * KDIM + (kt) * 32 + c * 8;         \
        const uint32_t doff = (uint32_t)(r * 112 + c * 16);                    \
        CP_ASYNC16(base + G_AH + doff, Ah + so);                               \
        CP_ASYNC16(base + G_AL + doff, Al + so);                               \
    }                                                                          \
    _Pragma("unroll")                                                          \
    for (int i = 0; i < 2; i++) {                                              \
        const int id = i * 256 + tid;                                          \
        const int r = id >> 4, c = id & 15;                                    \
        const size_t so = (size_t)((kt) * 32 + r) * SEQ + n0 + c * 8;          \
        const uint32_t doff = (uint32_t)(r * 272 + c * 16);                    \
        CP_ASYNC16(base + G_BH + doff, Bh + so);                               \
        CP_ASYNC16(base + G_BL + doff, Bl + so);                               \
    }                                                                          \
} while (0)

    G_CP(0, 0);
    CP_COMMIT();

    const int NKT = KDIM / 32;
    for (int kt = 0; kt < NKT; kt++) {
        __syncthreads();
        if (kt + 1 < NKT) { G_CP(kt + 1, (kt + 1) & 1); CP_COMMIT(); CP_WAIT(1); }
        else CP_WAIT(0);
        __syncthreads();

        const uint32_t base = sb + (kt & 1) * G_BUF;
#pragma unroll
        for (int ks = 0; ks < 2; ks++) {
            uint32_t aF[2][4], aL[2][4];
#pragma unroll
            for (int ms = 0; ms < 2; ms++) {
                const uint32_t ao = (uint32_t)((wm * 32 + ms * 16 + arow) * LAH + ks * 16 + ak8) * 2;
                LDSM_X4(aF[ms][0], aF[ms][1], aF[ms][2], aF[ms][3], base + G_AH + ao);
                LDSM_X4(aL[ms][0], aL[ms][1], aL[ms][2], aL[ms][3], base + G_AL + ao);
            }
#pragma unroll
            for (int nt16 = 0; nt16 < 4; nt16++) {
                uint32_t bH[4], bL[4];
                const uint32_t bo = (uint32_t)((ks * 16 + bk) * LBH + wn * 64 + nt16 * 16 + bn8) * 2;
                LDSM_X4T(bH[0], bH[1], bH[2], bH[3], base + G_BH + bo);
                LDSM_X4T(bL[0], bL[1], bL[2], bL[3], base + G_BL + bo);
#pragma unroll
                for (int ms = 0; ms < 2; ms++)
#pragma unroll
                    for (int s = 0; s < 2; s++) {
                        float* a4 = acc[ms][nt16 * 2 + s];
                        mma16816(a4, aF[ms], &bH[s * 2]);
                        mma16816(a4, aF[ms], &bL[s * 2]);
                        mma16816(a4, aL[ms], &bH[s * 2]);
                    }
            }
        }
    }

    __syncthreads();
    float* Cs = (float*)smg;
    {
        const int rr = lane >> 2, cc = (lane & 3) * 2;
#pragma unroll
        for (int ms = 0; ms < 2; ms++)
#pragma unroll
            for (int nt = 0; nt < 8; nt++) {
                const int r = wm * 32 + ms * 16 + rr;
                const int c = wn * 64 + nt * 8 + cc;
                Cs[r * 132 + c]           = acc[ms][nt][0];
                Cs[r * 132 + c + 1]       = acc[ms][nt][1];
                Cs[(r + 8) * 132 + c]     = acc[ms][nt][2];
                Cs[(r + 8) * 132 + c + 1] = acc[ms][nt][3];
            }
    }
    __syncthreads();
#pragma unroll
    for (int i = 0; i < 16; i++) {
        const int e = i * 256 + tid;
        const int r = e >> 5, c4 = (e & 31) * 4;
        float4 v = *(const float4*)&Cs[r * 132 + c4];
        const float bi = bias_s[r];
        v.x = alpha * (v.x + bi); v.y = alpha * (v.y + bi);
        v.z = alpha * (v.z + bi); v.w = alpha * (v.w + bi);
        const size_t go = (size_t)(m0 + r) * SEQ + n0 + c4;
        if (mode == 0) {
            *(float4*)&Cf[go] = v;
        } else if (mode == 1) {
            uint32_t h0, h1, l0, l1;
            split4(v, h0, h1, l0, l1);
            *(uint2*)&Ch[go] = make_uint2(h0, h1);
            *(uint2*)&Cl[go] = make_uint2(l0, l1);
        } else if (mode == 2) {
            uint32_t f0, f1;
            CVT_F16X2(f0, v.x, v.y);
            CVT_F16X2(f1, v.z, v.w);
            *(uint2*)&Ch[go] = make_uint2(f0, f1);
        } else {
            uint32_t h0, h1, l0, l1;
            split4_f16(v, h0, h1, l0, l1);
            *(uint2*)&Ch[go] = make_uint2(h0, h1);
            *(uint2*)&Cl[go] = make_uint2(l0, l1);
        }
    }
}

__global__ void __launch_bounds__(256, 2) gemm_qkv(
    const ushort_t* __restrict__ wh, const ushort_t* __restrict__ wl,
    const ushort_t* __restrict__ xh, const ushort_t* __restrict__ xl,
    const float* __restrict__ bq, const float* __restrict__ bk,
    const float* __restrict__ bv,
    ushort_t* __restrict__ ph, ushort_t* __restrict__ pl)
{
    const int gi = blockIdx.z >> 1, bb = blockIdx.z & 1;
    const size_t woff = (size_t)gi * WSZ;
    const size_t xoff = (size_t)gi * XSZ + (size_t)bb * ESZ;
    const float* bias = gi == 0 ? bq : (gi == 1 ? bk : bv);
    const float alpha = gi == 0 ? 0.125f * LOG2E : 1.0f;
    const int mode = gi == 0 ? 3 : 2;   // Q -> fp16 hi/lo, K/V -> fp16 single
    gemm_body(wh + woff, wl + woff, xh + xoff, xl + xoff, bias,
              nullptr, ph + xoff, pl + xoff, alpha, mode);
}
__global__ void __launch_bounds__(256, 2) gemm_wo(
    const ushort_t* __restrict__ wh, const ushort_t* __restrict__ wl,
    const ushort_t* __restrict__ ah, const ushort_t* __restrict__ al,
    const float* __restrict__ bo, float* __restrict__ out)
{
    const size_t off = (size_t)blockIdx.z * ESZ;
    gemm_body(wh, wl, ah + off, al + off, bo, out + off, nullptr, nullptr, 1.0f, 0);
}

// ---------------- flash attention: all-fp16 MMA path -------------------------
// QK 2-pass fp16 (Q hi/lo, K single), PV 1-pass fp16. 128-key staging in
// 64-key halves; mask single 128-row buffer; KV double-buffered (Kf, Vf).
#define PKH 136
#define KVA 17408            // one array (64 x 136 halves)
#define KVB2 34816           // buffer: Kf, Vf
#define MASK_OFF 69632       // 128 x 132 f32 = 67584 B
#define AT_SMEM 137216       // = MASK_OFF + 67584

__global__ void __launch_bounds__(256) attn_mma(
    const ushort_t* __restrict__ Qh, const ushort_t* __restrict__ Ql,
    const ushort_t* __restrict__ Kf, const ushort_t* __restrict__ Vf,
    const float* __restrict__ MASK,
    ushort_t* __restrict__ Oh, ushort_t* __restrict__ Ol)
{
    extern __shared__ char sma[];
    const uint32_t sb = smem_u32(sma);
    const int tid = threadIdx.x, wid = tid >> 5, lane = tid & 31;
    const int b = blockIdx.z, h = blockIdx.y, q0 = blockIdx.x * 128;

    const size_t hoff = ((size_t)b * EMB + h * DH) * SEQ;
    const float* Mg = MASK + (size_t)b * SEQ * SEQ;

#define A_CPKV(k0, buf) do {                                                   \
    const uint32_t base = sb + (buf) * KVB2;                                   \
    _Pragma("unroll")                                                          \
    for (int i = 0; i < 4; i++) {                                              \
        const int id = i * 256 + tid;                                          \
        const int r = id >> 4, c = id & 15;                                    \
        const size_t so = hoff + (size_t)r * SEQ + (k0) + c * 8;               \
        const uint32_t doff = (uint32_t)(r * 272 + c * 16);                    \
        CP_ASYNC16(base +       doff, Kf + so);                                \
        CP_ASYNC16(base + KVA + doff, Vf + so);                                \
    }                                                                          \
} while (0)

#define A_CPMASK(k0) do {                                                      \
    const uint32_t mb = sb + MASK_OFF;                                         \
    _Pragma("unroll")                                                          \
    for (int i = 0; i < 16; i++) {                                             \
        const int id = i * 256 + tid;                                          \
        const int r = id >> 5, c32 = id & 31;                                  \
        CP_ASYNC16(mb + (uint32_t)(r * 132 + c32 * 4) * 4,                     \
                   Mg + (size_t)((k0) + r) * SEQ + q0 + c32 * 4);              \
    }                                                                          \
} while (0)

    // ---- preamble: Q (into KV buf1) + mask0 (group A); KV0 (group B) ----
    {
        const uint32_t qb = sb + KVB2;
#pragma unroll
        for (int i = 0; i < 4; i++) {
            const int id = i * 256 + tid;
            const int r = id >> 4, c = id & 15;
            const size_t so = hoff + (size_t)r * SEQ + q0 + c * 8;
            const uint32_t doff = (uint32_t)(r * 272 + c * 16);
            CP_ASYNC16(qb + doff, Qh + so);
            CP_ASYNC16(qb + KVA + doff, Ql + so);
        }
    }
    A_CPMASK(0);
    CP_COMMIT();
    A_CPKV(0, 0);
    CP_COMMIT();
    CP_WAIT(1);
    __syncthreads();

    const int arow_k = (lane & 7) + ((lane >> 4) << 3);
    const int amcol  = ((lane >> 3) & 1) * 8;
    uint32_t qfh[4][4], qfl[4][4];
#pragma unroll
    for (int ks = 0; ks < 4; ks++) {
        const uint32_t ao = (uint32_t)((ks * 16 + arow_k) * PKH + wid * 16 + amcol) * 2;
        LDSM_X4T(qfh[ks][0], qfh[ks][1], qfh[ks][2], qfh[ks][3], sb + KVB2 + ao);
        LDSM_X4T(qfl[ks][0], qfl[ks][1], qfl[ks][2], qfl[ks][3], sb + KVB2 + KVA + ao);
    }
    __syncthreads();   // Q region free for KV buf1 (cp issued in iter 0)

    const int bj = lane >> 3, br = lane & 7;
    const int bk = (bj & 1) * 8 + br, bn8 = (bj >> 1) * 8;      // trans (K)
    const int bvrow = ((lane >> 4) & 1) * 8 + br;               // plain (V)
    const int bvk8  = ((lane >> 3) & 1) * 8;

    float o[8][4];
#pragma unroll
    for (int d = 0; d < 8; d++)
#pragma unroll
        for (int j = 0; j < 4; j++) o[d][j] = 0.f;
    float lsum0 = 0.f, lsum1 = 0.f;

    const int qr = wid * 16 + (lane >> 2);
    const int krow2 = 2 * (lane & 3);
    const float* Ms = (const float*)(sma + MASK_OFF);

    const int NT = SEQ / 128;
    for (int kt = 0; kt < NT; kt++) {
        CP_WAIT(0);
        __syncthreads();   // KV kt + mask kt resident

        const uint32_t kvb = sb + (kt & 1) * KVB2;

#pragma unroll
        for (int h2 = 0; h2 < 2; h2++) {
            // ---- mask (this half) -> accumulator init ----
            float s[8][4];
#pragma unroll
            for (int nt = 0; nt < 8; nt++) {
                const float* mp = Ms + (h2 * 64 + nt * 8 + krow2) * 132 + qr;
                s[nt][0] = mp[0]   * LOG2E;
                s[nt][1] = mp[132] * LOG2E;
                s[nt][2] = mp[8]   * LOG2E;
                s[nt][3] = mp[140] * LOG2E;
            }
            if (h2 == 1) {
                __syncthreads();   // all warps done with mask buffer
                if (kt + 1 < NT) {
                    A_CPKV((kt + 1) * 128, (kt + 1) & 1);
                    A_CPMASK((kt + 1) * 128);
                    CP_COMMIT();
                }
            }
            // ---- QK mma (2-pass fp16), 64 keys ----
#pragma unroll
            for (int ks = 0; ks < 4; ks++)
#pragma unroll
                for (int np = 0; np < 4; np++) {
                    uint32_t kf[4];
                    const uint32_t bo = (uint32_t)((ks * 16 + bk) * PKH
                                                   + h2 * 64 + np * 16 + bn8) * 2;
                    LDSM_X4T(kf[0], kf[1], kf[2], kf[3], kvb + bo);
#pragma unroll
                    for (int s2 = 0; s2 < 2; s2++) {
                        float* a4 = s[np * 2 + s2];
                        mma16816f(a4, qfh[ks], &kf[s2 * 2]);
                        mma16816f(a4, qfl[ks], &kf[s2 * 2]);
                    }
                }
            // ---- exp2 + row sums ----
            float rs0 = 0.f, rs1 = 0.f;
#pragma unroll
            for (int nt = 0; nt < 8; nt++) {
#pragma unroll
                for (int j = 0; j < 4; j++) EX2F(s[nt][j], s[nt][j]);
                rs0 += s[nt][0] + s[nt][1];
                rs1 += s[nt][2] + s[nt][3];
            }
            rs0 += __shfl_xor_sync(0xffffffffu, rs0, 1);
            rs0 += __shfl_xor_sync(0xffffffffu, rs0, 2);
            rs1 += __shfl_xor_sync(0xffffffffu, rs1, 1);
            rs1 += __shfl_xor_sync(0xffffffffu, rs1, 2);
            lsum0 += rs0;
            lsum1 += rs1;

            // ---- pack P as fp16 (single) ----
            uint32_t pa[4][4];
#pragma unroll
            for (int ks = 0; ks < 4; ks++) {
                const float* u = s[ks * 2];
                const float* w = s[ks * 2 + 1];
                CVT_F16X2(pa[ks][0], u[0], u[1]);
                CVT_F16X2(pa[ks][1], u[2], u[3]);
                CVT_F16X2(pa[ks][2], w[0], w[1]);
                CVT_F16X2(pa[ks][3], w[2], w[3]);
            }
            // ---- PV mma (1-pass fp16): O += P @ V ----
#pragma unroll
            for (int ks = 0; ks < 4; ks++)
#pragma unroll
                for (int dp = 0; dp < 4; dp++) {
                    uint32_t vf[4];
                    const uint32_t bo = (uint32_t)((dp * 16 + bvrow) * PKH
                                                   + h2 * 64 + ks * 16 + bvk8) * 2;
                    LDSM_X4(vf[0], vf[1], vf[2], vf[3], kvb + KVA + bo);
#pragma unroll
                    for (int s2 = 0; s2 < 2; s2++)
                        mma16816f(o[dp * 2 + s2], pa[ks], &vf[s2 * 2]);
                }
        }
    }

    // ---- normalize, transpose via smem, hi/lo coalesced store ----
    const float inv0 = 1.f / lsum0, inv1 = 1.f / lsum1;
    __syncthreads();
    float* Os = (float*)sma;   // [64 dh][132]
#pragma unroll
    for (int d = 0; d < 8; d++) {
        const int dc = d * 8 + krow2;
        Os[dc * 132 + qr]           = o[d][0] * inv0;
        Os[(dc + 1) * 132 + qr]     = o[d][1] * inv0;
        Os[dc * 132 + qr + 8]       = o[d][2] * inv1;
        Os[(dc + 1) * 132 + qr + 8] = o[d][3] * inv1;
    }
    __syncthreads();
#pragma unroll
    for (int i = 0; i < 8; i++) {
        const int e = i * 256 + tid;
        const int r = e >> 5, c4 = (e & 31) * 4;
        const float4 v = *(const float4*)&Os[r * 132 + c4];
        uint32_t h0, h1, l0, l1;
        split4(v, h0, h1, l0, l1);
        const size_t go = hoff + (size_t)r * SEQ + q0 + c4;
        *(uint2*)&Oh[go] = make_uint2(h0, h1);
        *(uint2*)&Ol[go] = make_uint2(l0, l1);
    }
}

// ---------------------------------------------------------------------------
extern "C" void kernel_launch(void* const* d_in, const int* in_sizes, int n_in,
                              void* d_out, int out_size)
{
    const float* q   = (const float*)d_in[0];
    const float* k   = (const float*)d_in[1];
    const float* v   = (const float*)d_in[2];
    const float* msk = (const float*)d_in[3];
    const float* Wq  = (const float*)d_in[4];
    const float* bq  = (const float*)d_in[5];
    const float* Wk  = (const float*)d_in[6];
    const float* bk  = (const float*)d_in[7];
    const float* Wv  = (const float*)d_in[8];
    const float* bv  = (const float*)d_in[9];
    const float* Wo  = (const float*)d_in[10];
    const float* bo  = (const float*)d_in[11];
    float* out = (float*)d_out;

    void *pwh, *pwl, *pxh, *pxl, *pph, *ppl, *path, *patl;
    cudaGetSymbolAddress(&pwh, g_wh);
    cudaGetSymbolAddress(&pwl, g_wl);
    cudaGetSymbolAddress(&pxh, g_xh);
    cudaGetSymbolAddress(&pxl, g_xl);
    cudaGetSymbolAddress(&pph, g_ph);
    cudaGetSymbolAddress(&ppl, g_pl);
    cudaGetSymbolAddress(&path, g_ath);
    cudaGetSymbolAddress(&patl, g_atl);

    ushort_t* wh = (ushort_t*)pwh;  ushort_t* wl = (ushort_t*)pwl;
    ushort_t* xh = (ushort_t*)pxh;  ushort_t* xl = (ushort_t*)pxl;
    ushort_t* ph = (ushort_t*)pph;  ushort_t* pl = (ushort_t*)ppl;
    ushort_t* ath = (ushort_t*)path; ushort_t* atl = (ushort_t*)patl;

    cudaFuncSetAttribute(gemm_qkv, cudaFuncAttributeMaxDynamicSharedMemorySize, GB_SMEM);
    cudaFuncSetAttribute(gemm_wo,  cudaFuncAttributeMaxDynamicSharedMemorySize, GB_SMEM);
    cudaFuncSetAttribute(attn_mma, cudaFuncAttributeMaxDynamicSharedMemorySize, AT_SMEM);

    // 1. converts
    to_hilo_w<<<dim3((unsigned)(WSZ / 1024), 4), 256>>>(Wq, Wk, Wv, Wo, wh, wl);
    to_hilo_x<<<dim3((unsigned)(XSZ / 1024), 3), 256>>>(q, k, v, xh, xl);

    // 2. merged QKV projections (Q -> fp16 hi/lo, K/V -> fp16 single)
    dim3 gq(SEQ / 128, EMB / 128, 6);
    gemm_qkv<<<gq, 256, GB_SMEM>>>(wh, wl, xh, xl, bq, bk, bv, ph, pl);

    // 3. attention
    dim3 ga(SEQ / 128, NH, BATCH);
    attn_mma<<<ga, 256, AT_SMEM>>>(ph + 0 * XSZ, pl + 0 * XSZ,
                                   ph + 1 * XSZ, ph + 2 * XSZ,
                                   msk, ath, atl);

    // 4. output projection
    dim3 go(SEQ / 128, EMB / 128, BATCH);
    gemm_wo<<<go, 256, GB_SMEM>>>(wh + 3 * WSZ, wl + 3 * WSZ, ath, atl, bo, out);
}